// round 1
// baseline (speedup 1.0000x reference)
#include <cuda_runtime.h>
#include <math.h>

#define B_    4
#define NSEQ  4096
#define MTOT  (B_*NSEQ)
#define D_    256
#define NOUT  128
#define EPS   1e-5f
#define EROWS 16

// ---- scratch (static device globals; no allocation allowed) ----
__device__ float g_Q [(size_t)MTOT*D_];
__device__ float g_K [(size_t)MTOT*D_];
__device__ float g_V [(size_t)MTOT*D_];
__device__ float g_tQ[(size_t)MTOT*D_];
__device__ float g_tK[(size_t)MTOT*D_];
__device__ float g_Qh[(size_t)MTOT*D_];

// ================= projection: C = X@W + b (optionally T = tanh(C)) =========
template<bool STORE_TANH>
__global__ __launch_bounds__(256) void proj_kernel(
    const float* __restrict__ X, const float* __restrict__ W,
    const float* __restrict__ bias, float* __restrict__ C, float* __restrict__ T)
{
    const int BM=64, BN=64, BK=16;
    __shared__ float Xs[BK][BM];
    __shared__ float Ws[BK][BN];
    int tid = threadIdx.x;
    int tx = tid & 15, ty = tid >> 4;
    int row0 = blockIdx.y * BM;
    int col0 = blockIdx.x * BN;
    int lr = tid >> 2, lc4 = tid & 3;     // X tile loader: 64 rows x 16 cols
    int wkr = tid >> 4, wc4 = tid & 15;   // W tile loader: 16 rows x 64 cols
    float acc[4][4] = {};

    for (int k0 = 0; k0 < D_; k0 += BK) {
        float4 v = *(const float4*)(X + (size_t)(row0+lr)*D_ + k0 + lc4*4);
        Xs[lc4*4+0][lr]=v.x; Xs[lc4*4+1][lr]=v.y; Xs[lc4*4+2][lr]=v.z; Xs[lc4*4+3][lr]=v.w;
        *(float4*)&Ws[wkr][wc4*4] = *(const float4*)(W + (size_t)(k0+wkr)*D_ + col0 + wc4*4);
        __syncthreads();
        #pragma unroll
        for (int kk=0; kk<BK; kk++) {
            float4 a4 = *(const float4*)&Xs[kk][ty*4];
            float4 w4 = *(const float4*)&Ws[kk][tx*4];
            float av[4]={a4.x,a4.y,a4.z,a4.w}, wv[4]={w4.x,w4.y,w4.z,w4.w};
            #pragma unroll
            for (int i=0;i<4;i++)
                #pragma unroll
                for (int j=0;j<4;j++) acc[i][j] += av[i]*wv[j];
        }
        __syncthreads();
    }
    #pragma unroll
    for (int i=0;i<4;i++) {
        size_t r = row0 + ty*4 + i;
        #pragma unroll
        for (int j=0;j<4;j++) {
            int cix = col0 + tx*4 + j;
            float val = acc[i][j] + bias[cix];
            C[r*D_ + cix] = val;
            if (STORE_TANH) T[r*D_ + cix] = tanhf(val);
        }
    }
}

// ====== dual-GEMM scores: attn_raw = (Q@K^T) * ((tQ@tK^T)+1) * 0.5/16 =======
__global__ __launch_bounds__(256) void scores_kernel(
    const float* __restrict__ Qg, const float* __restrict__ tQg,
    const float* __restrict__ Kg, const float* __restrict__ tKg,
    float* __restrict__ attn)
{
    const int BM=64, BN=64, BK=16;
    __shared__ float Qs[BK][BM], tQs[BK][BM], Ks[BK][BN], tKs[BK][BN];
    int tid = threadIdx.x;
    int tx = tid & 15, ty = tid >> 4;
    size_t boff = (size_t)blockIdx.z * NSEQ * D_;
    const float* Q  = Qg  + boff;
    const float* tQ = tQg + boff;
    const float* K  = Kg  + boff;
    const float* tK = tKg + boff;
    int q0 = blockIdx.y*BM, c0 = blockIdx.x*BN;
    int lr = tid>>2, lc4 = tid&3;
    float acc[4][4]={}, act[4][4]={};

    for (int k0=0; k0<D_; k0+=BK) {
        float4 v;
        v = *(const float4*)(Q  + (size_t)(q0+lr)*D_ + k0 + lc4*4);
        Qs [lc4*4+0][lr]=v.x; Qs [lc4*4+1][lr]=v.y; Qs [lc4*4+2][lr]=v.z; Qs [lc4*4+3][lr]=v.w;
        v = *(const float4*)(tQ + (size_t)(q0+lr)*D_ + k0 + lc4*4);
        tQs[lc4*4+0][lr]=v.x; tQs[lc4*4+1][lr]=v.y; tQs[lc4*4+2][lr]=v.z; tQs[lc4*4+3][lr]=v.w;
        v = *(const float4*)(K  + (size_t)(c0+lr)*D_ + k0 + lc4*4);
        Ks [lc4*4+0][lr]=v.x; Ks [lc4*4+1][lr]=v.y; Ks [lc4*4+2][lr]=v.z; Ks [lc4*4+3][lr]=v.w;
        v = *(const float4*)(tK + (size_t)(c0+lr)*D_ + k0 + lc4*4);
        tKs[lc4*4+0][lr]=v.x; tKs[lc4*4+1][lr]=v.y; tKs[lc4*4+2][lr]=v.z; tKs[lc4*4+3][lr]=v.w;
        __syncthreads();
        #pragma unroll
        for (int kk=0; kk<BK; kk++) {
            float4 a4 = *(const float4*)&Qs [kk][ty*4];
            float4 t4 = *(const float4*)&tQs[kk][ty*4];
            float4 b4 = *(const float4*)&Ks [kk][tx*4];
            float4 u4 = *(const float4*)&tKs[kk][tx*4];
            float av[4]={a4.x,a4.y,a4.z,a4.w}, tv[4]={t4.x,t4.y,t4.z,t4.w};
            float bv[4]={b4.x,b4.y,b4.z,b4.w}, uv[4]={u4.x,u4.y,u4.z,u4.w};
            #pragma unroll
            for (int i=0;i<4;i++)
                #pragma unroll
                for (int j=0;j<4;j++) {
                    acc[i][j] += av[i]*bv[j];
                    act[i][j] += tv[i]*uv[j];
                }
        }
        __syncthreads();
    }
    float* orow = attn + (size_t)blockIdx.z * NSEQ * NSEQ;
    #pragma unroll
    for (int i=0;i<4;i++) {
        float4 o;
        o.x = acc[i][0]*(act[i][0]+1.0f)*0.03125f;
        o.y = acc[i][1]*(act[i][1]+1.0f)*0.03125f;
        o.z = acc[i][2]*(act[i][2]+1.0f)*0.03125f;
        o.w = acc[i][3]*(act[i][3]+1.0f)*0.03125f;
        *(float4*)(orow + (size_t)(q0+ty*4+i)*NSEQ + c0 + tx*4) = o;
    }
}

// ======================= in-place row softmax (4096) ========================
__device__ __forceinline__ float blockMax256(float v) {
    __shared__ float sh[8];
    #pragma unroll
    for (int o=16;o>0;o>>=1) v = fmaxf(v, __shfl_xor_sync(0xffffffffu, v, o));
    if ((threadIdx.x & 31)==0) sh[threadIdx.x>>5] = v;
    __syncthreads();
    float m = sh[0];
    #pragma unroll
    for (int w=1;w<8;w++) m = fmaxf(m, sh[w]);
    __syncthreads();
    return m;
}
__device__ __forceinline__ float blockSum256(float v) {
    __shared__ float sh[8];
    #pragma unroll
    for (int o=16;o>0;o>>=1) v += __shfl_xor_sync(0xffffffffu, v, o);
    if ((threadIdx.x & 31)==0) sh[threadIdx.x>>5] = v;
    __syncthreads();
    float s = sh[0];
    #pragma unroll
    for (int w=1;w<8;w++) s += sh[w];
    __syncthreads();
    return s;
}
__global__ __launch_bounds__(256) void softmax_kernel(float* __restrict__ attn)
{
    float4* p = (float4*)(attn + (size_t)blockIdx.x * NSEQ);
    int tid = threadIdx.x;
    float4 v[4];
    #pragma unroll
    for (int t=0;t<4;t++) v[t] = p[tid + 256*t];
    float m = -1e30f;
    #pragma unroll
    for (int t=0;t<4;t++) {
        m = fmaxf(m, fmaxf(fmaxf(v[t].x, v[t].y), fmaxf(v[t].z, v[t].w)));
    }
    m = blockMax256(m);
    float s = 0.f;
    #pragma unroll
    for (int t=0;t<4;t++) {
        v[t].x = __expf(v[t].x - m); v[t].y = __expf(v[t].y - m);
        v[t].z = __expf(v[t].z - m); v[t].w = __expf(v[t].w - m);
        s += v[t].x + v[t].y + v[t].z + v[t].w;
    }
    s = blockSum256(s);
    float inv = 1.0f / s;
    #pragma unroll
    for (int t=0;t<4;t++) {
        v[t].x *= inv; v[t].y *= inv; v[t].z *= inv; v[t].w *= inv;
        p[tid + 256*t] = v[t];
    }
}

// ========================= Qhat = attn @ V ==================================
__global__ __launch_bounds__(256) void av_kernel(
    const float* __restrict__ attn, const float* __restrict__ Vg, float* __restrict__ Cg)
{
    const int BM=64, BN=128, BK=16;
    __shared__ float As[BK][BM];
    __shared__ float Bs[BK][BN];
    int tid = threadIdx.x;
    int tx = tid & 15, ty = tid >> 4;          // thread tile 4 x 8
    size_t b = blockIdx.z;
    const float* A  = attn + b*(size_t)NSEQ*NSEQ;
    const float* Bv = Vg   + b*(size_t)NSEQ*D_;
    float*       C  = Cg   + b*(size_t)NSEQ*D_;
    int row0 = blockIdx.y*BM, col0 = blockIdx.x*BN;
    int lr = tid>>2, lc4 = tid&3;
    float acc[4][8] = {};

    for (int k0=0; k0<NSEQ; k0+=BK) {
        float4 v = *(const float4*)(A + (size_t)(row0+lr)*NSEQ + k0 + lc4*4);
        As[lc4*4+0][lr]=v.x; As[lc4*4+1][lr]=v.y; As[lc4*4+2][lr]=v.z; As[lc4*4+3][lr]=v.w;
        #pragma unroll
        for (int t=0;t<2;t++) {
            int idx = tid + t*256;
            int kr = idx>>5, c4 = idx&31;
            *(float4*)&Bs[kr][c4*4] =
                *(const float4*)(Bv + (size_t)(k0+kr)*D_ + col0 + c4*4);
        }
        __syncthreads();
        #pragma unroll
        for (int kk=0; kk<BK; kk++) {
            float4 a4  = *(const float4*)&As[kk][ty*4];
            float4 b4l = *(const float4*)&Bs[kk][tx*8];
            float4 b4h = *(const float4*)&Bs[kk][tx*8+4];
            float av[4]={a4.x,a4.y,a4.z,a4.w};
            float bv[8]={b4l.x,b4l.y,b4l.z,b4l.w,b4h.x,b4h.y,b4h.z,b4h.w};
            #pragma unroll
            for (int i=0;i<4;i++)
                #pragma unroll
                for (int j=0;j<8;j++) acc[i][j] += av[i]*bv[j];
        }
        __syncthreads();
    }
    #pragma unroll
    for (int i=0;i<4;i++) {
        size_t r = row0 + ty*4 + i;
        float4 o1 = {acc[i][0],acc[i][1],acc[i][2],acc[i][3]};
        float4 o2 = {acc[i][4],acc[i][5],acc[i][6],acc[i][7]};
        *(float4*)(C + r*D_ + col0 + tx*8)     = o1;
        *(float4*)(C + r*D_ + col0 + tx*8 + 4) = o2;
    }
}

// ===================== fused gate epilogue ==================================
__device__ __forceinline__ void blockSum2_128(float& a, float& b) {
    __shared__ float sh[8];
    #pragma unroll
    for (int o=16;o>0;o>>=1) {
        a += __shfl_xor_sync(0xffffffffu, a, o);
        b += __shfl_xor_sync(0xffffffffu, b, o);
    }
    if ((threadIdx.x & 31)==0) { sh[threadIdx.x>>5]=a; sh[4+(threadIdx.x>>5)]=b; }
    __syncthreads();
    a = sh[0]+sh[1]+sh[2]+sh[3];
    b = sh[4]+sh[5]+sh[6]+sh[7];
    __syncthreads();
}

__global__ __launch_bounds__(128) void epilogue_kernel(
    const float* __restrict__ Qg, const float* __restrict__ Qhg,
    const float* __restrict__ W1, const float* __restrict__ b1,
    const float* __restrict__ W2, const float* __restrict__ b2,
    const float* __restrict__ W3, const float* __restrict__ b3,
    const float* __restrict__ Wc, const float* __restrict__ bc,
    const float* __restrict__ Wf, const float* __restrict__ bf,
    const float* __restrict__ gg, const float* __restrict__ gb,
    const float* __restrict__ eg, const float* __restrict__ eb,
    float* __restrict__ out)
{
    __shared__ float Qs[EROWS][D_];
    __shared__ float Qh[EROWS][D_];
    __shared__ float ges[EROWS][NOUT];
    int j = threadIdx.x;                       // output channel 0..127
    size_t row0 = (size_t)blockIdx.x * EROWS;

    {
        const float4* s1 = (const float4*)(Qg  + row0*D_);
        const float4* s2 = (const float4*)(Qhg + row0*D_);
        float4* dQ = (float4*)&Qs[0][0];
        float4* dH = (float4*)&Qh[0][0];
        for (int t=j; t<EROWS*D_/4; t+=128) { dQ[t]=s1[t]; dH[t]=s2[t]; }
    }
    __syncthreads();

    float acc1[EROWS]={}, acc2[EROWS]={}, acc3[EROWS]={}, accF[EROWS]={};
    for (int c=0; c<D_; c+=4) {
        float w1v[4], w2v[4], w3v[4], wfv[4];
        #pragma unroll
        for (int u=0;u<4;u++) {
            w1v[u]=W1[(c+u)*NOUT+j]; w2v[u]=W2[(c+u)*NOUT+j];
            w3v[u]=W3[(c+u)*NOUT+j]; wfv[u]=Wf[(c+u)*NOUT+j];
        }
        #pragma unroll
        for (int r=0;r<EROWS;r++) {
            float4 q = *(const float4*)&Qs[r][c];
            float4 h = *(const float4*)&Qh[r][c];
            acc1[r] += q.x*w1v[0]+q.y*w1v[1]+q.z*w1v[2]+q.w*w1v[3];
            accF[r] += q.x*wfv[0]+q.y*wfv[1]+q.z*wfv[2]+q.w*wfv[3];
            acc2[r] += h.x*w2v[0]+h.y*w2v[1]+h.z*w2v[2]+h.w*w2v[3];
            acc3[r] += h.x*w3v[0]+h.y*w3v[1]+h.z*w3v[2]+h.w*w3v[3];
        }
    }

    float bb1=b1[j], bb2=b2[j], bb3=b3[j], bbf=bf[j], bbc=bc[j];
    float ggj=gg[j], gbj=gb[j], egj=eg[j], ebj=eb[j];

    #pragma unroll 1
    for (int r=0;r<EROWS;r++) {
        float gin = fmaxf(fmaxf(acc1[r]+bb1,0.f) + fmaxf(acc2[r]+bb2,0.f), 0.f);
        float ein = fmaxf(acc3[r]+bb3, 0.f);
        float s1 = gin, s2 = gin*gin;
        blockSum2_128(s1, s2);
        float mu  = s1*(1.0f/NOUT);
        float var = s2*(1.0f/NOUT) - mu*mu;
        float G = (gin-mu)*rsqrtf(var+EPS)*ggj + gbj;
        s1 = ein; s2 = ein*ein;
        blockSum2_128(s1, s2);
        mu  = s1*(1.0f/NOUT);
        var = s2*(1.0f/NOUT) - mu*mu;
        float E = (ein-mu)*rsqrtf(var+EPS)*egj + ebj;
        ges[r][j] = G*E;
        accF[r] = fmaxf(accF[r]+bbf, 0.f);
    }
    __syncthreads();

    float accC[EROWS]={};
    for (int k=0;k<NOUT;k++) {
        float wc = Wc[k*NOUT+j];
        #pragma unroll
        for (int r=0;r<EROWS;r++) accC[r] += ges[r][k]*wc;
    }
    #pragma unroll
    for (int r=0;r<EROWS;r++)
        out[(row0+r)*NOUT + j] = accF[r] + fmaxf(accC[r]+bbc, 0.f);
}

// ============================================================================
extern "C" void kernel_launch(void* const* d_in, const int* in_sizes, int n_in,
                              void* d_out, int out_size)
{
    const float* x1 = (const float*)d_in[0];
    const float* x2 = (const float*)d_in[1];
    const float* W_q=(const float*)d_in[2];  const float* b_q=(const float*)d_in[3];
    const float* W_k=(const float*)d_in[4];  const float* b_k=(const float*)d_in[5];
    const float* W_v=(const float*)d_in[6];  const float* b_v=(const float*)d_in[7];
    const float* W1 =(const float*)d_in[8];  const float* b1 =(const float*)d_in[9];
    const float* W2 =(const float*)d_in[10]; const float* b2 =(const float*)d_in[11];
    const float* W3 =(const float*)d_in[12]; const float* b3 =(const float*)d_in[13];
    const float* gg =(const float*)d_in[14]; const float* gb =(const float*)d_in[15];
    const float* eg =(const float*)d_in[16]; const float* eb =(const float*)d_in[17];
    const float* Wc =(const float*)d_in[18]; const float* bc =(const float*)d_in[19];
    const float* Wf =(const float*)d_in[20]; const float* bf =(const float*)d_in[21];

    float* out     = (float*)d_out;
    float* outMain = out;                                // [16384,128]
    float* attn    = out + (size_t)MTOT*NOUT;            // [4,4096,4096]

    float *Q,*K,*V,*tQ,*tK,*Qh;
    cudaGetSymbolAddress((void**)&Q,  g_Q);
    cudaGetSymbolAddress((void**)&K,  g_K);
    cudaGetSymbolAddress((void**)&V,  g_V);
    cudaGetSymbolAddress((void**)&tQ, g_tQ);
    cudaGetSymbolAddress((void**)&tK, g_tK);
    cudaGetSymbolAddress((void**)&Qh, g_Qh);

    dim3 pg(D_/64, MTOT/64);
    proj_kernel<true ><<<pg, 256>>>(x2, W_q, b_q, Q, tQ);
    proj_kernel<true ><<<pg, 256>>>(x1, W_k, b_k, K, tK);
    proj_kernel<false><<<pg, 256>>>(x1, W_v, b_v, V, nullptr);

    scores_kernel<<<dim3(NSEQ/64, NSEQ/64, B_), 256>>>(Q, tQ, K, tK, attn);
    softmax_kernel<<<MTOT, 256>>>(attn);
    av_kernel<<<dim3(D_/128, NSEQ/64, B_), 256>>>(attn, V, Qh);

    epilogue_kernel<<<MTOT/EROWS, 128>>>(Q, Qh, W1,b1, W2,b2, W3,b3,
                                         Wc,bc, Wf,bf, gg,gb, eg,eb, outMain);
}

// round 2
// speedup vs baseline: 1.5125x; 1.5125x over previous
#include <cuda_runtime.h>
#include <cuda_bf16.h>
#include <math.h>

#define B_    4
#define NSEQ  4096
#define MTOT  (B_*NSEQ)
#define D_    256
#define NOUT  128
#define EPS   1e-5f
#define EROWS 16

typedef __nv_bfloat16 bf16;

// ---- scratch (static device globals; no allocation allowed) ----
__device__ float g_Q [(size_t)MTOT*D_];
__device__ float g_Qh[(size_t)MTOT*D_];
__device__ bf16 g_Qhi [(size_t)MTOT*D_], g_Qlo [(size_t)MTOT*D_];
__device__ bf16 g_tQhi[(size_t)MTOT*D_], g_tQlo[(size_t)MTOT*D_];
__device__ bf16 g_Khi [(size_t)MTOT*D_], g_Klo [(size_t)MTOT*D_];
__device__ bf16 g_tKhi[(size_t)MTOT*D_], g_tKlo[(size_t)MTOT*D_];
__device__ bf16 g_Vthi[(size_t)MTOT*D_], g_Vtlo[(size_t)MTOT*D_];   // transposed [B][D][NSEQ]
__device__ bf16 g_Phi [(size_t)B_*NSEQ*NSEQ], g_Plo[(size_t)B_*NSEQ*NSEQ];

__device__ __forceinline__ void split_bf16(float x, bf16& h, bf16& l) {
    h = __float2bfloat16(x);
    l = __float2bfloat16(x - __bfloat162float(h));
}

// bf16 m16n8k16 mma, fp32 accum
__device__ __forceinline__ void mma16816(float* d, const unsigned* a, const unsigned* b) {
    asm volatile(
        "mma.sync.aligned.m16n8k16.row.col.f32.bf16.bf16.f32 "
        "{%0,%1,%2,%3}, {%4,%5,%6,%7}, {%8,%9}, {%0,%1,%2,%3};\n"
        : "+f"(d[0]), "+f"(d[1]), "+f"(d[2]), "+f"(d[3])
        : "r"(a[0]), "r"(a[1]), "r"(a[2]), "r"(a[3]), "r"(b[0]), "r"(b[1]));
}

// ================= projection: C = X@W + b =================================
// MODE 0 (Q): f32 out + Qhi/Qlo + tanh hi/lo
// MODE 1 (K): Khi/Klo + tanh hi/lo
// MODE 2 (V): transposed Vt hi/lo
template<int MODE>
__global__ __launch_bounds__(256) void proj_kernel(
    const float* __restrict__ X, const float* __restrict__ W,
    const float* __restrict__ bias, float* __restrict__ Cf,
    bf16* __restrict__ H1, bf16* __restrict__ L1,
    bf16* __restrict__ H2, bf16* __restrict__ L2)
{
    const int BM=64, BN=64, BK=16;
    __shared__ float Xs[BK][BM];
    __shared__ float Ws[BK][BN];
    int tid = threadIdx.x;
    int tx = tid & 15, ty = tid >> 4;
    int row0 = blockIdx.y * BM;
    int col0 = blockIdx.x * BN;
    int lr = tid >> 2, lc4 = tid & 3;
    int wkr = tid >> 4, wc4 = tid & 15;
    float acc[4][4] = {};

    for (int k0 = 0; k0 < D_; k0 += BK) {
        float4 v = *(const float4*)(X + (size_t)(row0+lr)*D_ + k0 + lc4*4);
        Xs[lc4*4+0][lr]=v.x; Xs[lc4*4+1][lr]=v.y; Xs[lc4*4+2][lr]=v.z; Xs[lc4*4+3][lr]=v.w;
        *(float4*)&Ws[wkr][wc4*4] = *(const float4*)(W + (size_t)(k0+wkr)*D_ + col0 + wc4*4);
        __syncthreads();
        #pragma unroll
        for (int kk=0; kk<BK; kk++) {
            float4 a4 = *(const float4*)&Xs[kk][ty*4];
            float4 w4 = *(const float4*)&Ws[kk][tx*4];
            float av[4]={a4.x,a4.y,a4.z,a4.w}, wv[4]={w4.x,w4.y,w4.z,w4.w};
            #pragma unroll
            for (int i=0;i<4;i++)
                #pragma unroll
                for (int j=0;j<4;j++) acc[i][j] += av[i]*wv[j];
        }
        __syncthreads();
    }
    #pragma unroll
    for (int i=0;i<4;i++) {
        size_t r = row0 + ty*4 + i;
        #pragma unroll
        for (int j=0;j<4;j++) {
            int cix = col0 + tx*4 + j;
            float val = acc[i][j] + bias[cix];
            if (MODE == 0) {
                Cf[r*D_ + cix] = val;
                bf16 h,l; split_bf16(val, h, l);
                H1[r*D_+cix]=h; L1[r*D_+cix]=l;
                float t = tanhf(val);
                split_bf16(t, h, l);
                H2[r*D_+cix]=h; L2[r*D_+cix]=l;
            } else if (MODE == 1) {
                bf16 h,l; split_bf16(val, h, l);
                H1[r*D_+cix]=h; L1[r*D_+cix]=l;
                float t = tanhf(val);
                split_bf16(t, h, l);
                H2[r*D_+cix]=h; L2[r*D_+cix]=l;
            } else {
                int b = (int)(r >> 12), s = (int)(r & 4095);
                size_t ti = ((size_t)b*D_ + cix)*NSEQ + s;
                bf16 h,l; split_bf16(val, h, l);
                H1[ti]=h; L1[ti]=l;
            }
        }
    }
}

// ====== dual-GEMM scores via bf16 mma, hi/lo split ==========================
// smem: 8 matrices [128][40] bf16 (Qhi,Qlo,tQhi,tQlo,Khi,Klo,tKhi,tKlo)
#define SMM(mat,row,col) (sm + (mat)*5120 + (row)*40 + (col))

__global__ __launch_bounds__(512,1) void scores_mma_kernel(
    const bf16* __restrict__ Qhi, const bf16* __restrict__ Qlo,
    const bf16* __restrict__ tQhi,const bf16* __restrict__ tQlo,
    const bf16* __restrict__ Khi, const bf16* __restrict__ Klo,
    const bf16* __restrict__ tKhi,const bf16* __restrict__ tKlo,
    float* __restrict__ attn)
{
    extern __shared__ __align__(16) bf16 sm[];
    const int tid = threadIdx.x;
    const int warp = tid >> 5, lane = tid & 31;
    const int wm = warp >> 2, wn = warp & 3;
    const int g = lane >> 2, t4 = lane & 3;
    const int bz = blockIdx.z;
    const int q0 = blockIdx.y * 128, c0 = blockIdx.x * 128;

    const bf16* Ap[4] = { Qhi + ((size_t)bz*NSEQ + q0)*D_,  Qlo + ((size_t)bz*NSEQ + q0)*D_,
                          tQhi + ((size_t)bz*NSEQ + q0)*D_, tQlo + ((size_t)bz*NSEQ + q0)*D_ };
    const bf16* Bp[4] = { Khi + ((size_t)bz*NSEQ + c0)*D_,  Klo + ((size_t)bz*NSEQ + c0)*D_,
                          tKhi + ((size_t)bz*NSEQ + c0)*D_, tKlo + ((size_t)bz*NSEQ + c0)*D_ };

    float accQ[2][4][4] = {};
    float accT[2][4][4] = {};

    for (int kc = 0; kc < D_; kc += 32) {
        for (int i = tid; i < 4096; i += 512) {
            int mat = i >> 9, rem = i & 511, row = rem >> 2, q = rem & 3;
            const bf16* src = (mat < 4 ? Ap[mat] : Bp[mat-4]) + (size_t)row*D_ + kc + q*8;
            *(uint4*)SMM(mat, row, q*8) = *(const uint4*)src;
        }
        __syncthreads();
        #pragma unroll
        for (int ks = 0; ks < 2; ks++) {
            const int kb = ks*16 + 2*t4;
            unsigned bF[4][4][2];
            #pragma unroll
            for (int mat = 0; mat < 4; mat++)
                #pragma unroll
                for (int nt = 0; nt < 4; nt++) {
                    int n = wn*32 + nt*8 + g;
                    bF[mat][nt][0] = *(const unsigned*)SMM(4+mat, n, kb);
                    bF[mat][nt][1] = *(const unsigned*)SMM(4+mat, n, kb+8);
                }
            #pragma unroll
            for (int mt = 0; mt < 2; mt++) {
                int r = wm*32 + mt*16 + g;
                unsigned a[4];
                // Q hi
                a[0]=*(const unsigned*)SMM(0,r,kb);   a[1]=*(const unsigned*)SMM(0,r+8,kb);
                a[2]=*(const unsigned*)SMM(0,r,kb+8); a[3]=*(const unsigned*)SMM(0,r+8,kb+8);
                #pragma unroll
                for (int nt=0; nt<4; nt++) {
                    mma16816(accQ[mt][nt], a, bF[0][nt]);
                    mma16816(accQ[mt][nt], a, bF[1][nt]);
                }
                // Q lo
                a[0]=*(const unsigned*)SMM(1,r,kb);   a[1]=*(const unsigned*)SMM(1,r+8,kb);
                a[2]=*(const unsigned*)SMM(1,r,kb+8); a[3]=*(const unsigned*)SMM(1,r+8,kb+8);
                #pragma unroll
                for (int nt=0; nt<4; nt++) mma16816(accQ[mt][nt], a, bF[0][nt]);
                // tanh hi
                a[0]=*(const unsigned*)SMM(2,r,kb);   a[1]=*(const unsigned*)SMM(2,r+8,kb);
                a[2]=*(const unsigned*)SMM(2,r,kb+8); a[3]=*(const unsigned*)SMM(2,r+8,kb+8);
                #pragma unroll
                for (int nt=0; nt<4; nt++) {
                    mma16816(accT[mt][nt], a, bF[2][nt]);
                    mma16816(accT[mt][nt], a, bF[3][nt]);
                }
                // tanh lo
                a[0]=*(const unsigned*)SMM(3,r,kb);   a[1]=*(const unsigned*)SMM(3,r+8,kb);
                a[2]=*(const unsigned*)SMM(3,r,kb+8); a[3]=*(const unsigned*)SMM(3,r+8,kb+8);
                #pragma unroll
                for (int nt=0; nt<4; nt++) mma16816(accT[mt][nt], a, bF[2][nt]);
            }
        }
        __syncthreads();
    }

    float* ob = attn + (size_t)bz*NSEQ*NSEQ;
    #pragma unroll
    for (int mt=0; mt<2; mt++)
        #pragma unroll
        for (int nt=0; nt<4; nt++) {
            int r = q0 + wm*32 + mt*16 + g;
            int c = c0 + wn*32 + nt*8 + 2*t4;
            const float* aq = accQ[mt][nt];
            const float* at = accT[mt][nt];
            float2 v0 = { aq[0]*(at[0]+1.0f)*0.03125f, aq[1]*(at[1]+1.0f)*0.03125f };
            float2 v1 = { aq[2]*(at[2]+1.0f)*0.03125f, aq[3]*(at[3]+1.0f)*0.03125f };
            *(float2*)(ob + (size_t)r*NSEQ + c)     = v0;
            *(float2*)(ob + (size_t)(r+8)*NSEQ + c) = v1;
        }
}

// ======================= in-place row softmax (4096) + hi/lo ================
__device__ __forceinline__ float blockMax256(float v) {
    __shared__ float sh[8];
    #pragma unroll
    for (int o=16;o>0;o>>=1) v = fmaxf(v, __shfl_xor_sync(0xffffffffu, v, o));
    if ((threadIdx.x & 31)==0) sh[threadIdx.x>>5] = v;
    __syncthreads();
    float m = sh[0];
    #pragma unroll
    for (int w=1;w<8;w++) m = fmaxf(m, sh[w]);
    __syncthreads();
    return m;
}
__device__ __forceinline__ float blockSum256(float v) {
    __shared__ float sh[8];
    #pragma unroll
    for (int o=16;o>0;o>>=1) v += __shfl_xor_sync(0xffffffffu, v, o);
    if ((threadIdx.x & 31)==0) sh[threadIdx.x>>5] = v;
    __syncthreads();
    float s = sh[0];
    #pragma unroll
    for (int w=1;w<8;w++) s += sh[w];
    __syncthreads();
    return s;
}
__global__ __launch_bounds__(256) void softmax_kernel(
    float* __restrict__ attn, bf16* __restrict__ Phi, bf16* __restrict__ Plo)
{
    size_t rb = (size_t)blockIdx.x * NSEQ;
    float4* p = (float4*)(attn + rb);
    int tid = threadIdx.x;
    float4 v[4];
    #pragma unroll
    for (int t=0;t<4;t++) v[t] = p[tid + 256*t];
    float m = -1e30f;
    #pragma unroll
    for (int t=0;t<4;t++)
        m = fmaxf(m, fmaxf(fmaxf(v[t].x, v[t].y), fmaxf(v[t].z, v[t].w)));
    m = blockMax256(m);
    float s = 0.f;
    #pragma unroll
    for (int t=0;t<4;t++) {
        v[t].x = __expf(v[t].x - m); v[t].y = __expf(v[t].y - m);
        v[t].z = __expf(v[t].z - m); v[t].w = __expf(v[t].w - m);
        s += v[t].x + v[t].y + v[t].z + v[t].w;
    }
    s = blockSum256(s);
    float inv = 1.0f / s;
    #pragma unroll
    for (int t=0;t<4;t++) {
        v[t].x *= inv; v[t].y *= inv; v[t].z *= inv; v[t].w *= inv;
        p[tid + 256*t] = v[t];
        int idx = (tid + 256*t)*4;
        float f[4] = {v[t].x, v[t].y, v[t].z, v[t].w};
        bf16 h[4], l[4];
        #pragma unroll
        for (int u=0;u<4;u++) split_bf16(f[u], h[u], l[u]);
        __nv_bfloat162 h01; h01.x=h[0]; h01.y=h[1];
        __nv_bfloat162 h23; h23.x=h[2]; h23.y=h[3];
        __nv_bfloat162 l01; l01.x=l[0]; l01.y=l[1];
        __nv_bfloat162 l23; l23.x=l[2]; l23.y=l[3];
        __nv_bfloat162* hp = (__nv_bfloat162*)(Phi + rb + idx);
        __nv_bfloat162* lp = (__nv_bfloat162*)(Plo + rb + idx);
        hp[0]=h01; hp[1]=h23; lp[0]=l01; lp[1]=l23;
    }
}

// ========================= Qhat = attn @ V (bf16 mma) =======================
// smem: A = Phi,Plo [128][40] at 0,5120 ; B = Vthi,Vtlo [256][40] at 10240,20480
#define SMA(mat,row,col) (sm + (mat)*5120 + (row)*40 + (col))
#define SMB(mat,row,col) (sm + 10240 + (mat)*10240 + (row)*40 + (col))

__global__ __launch_bounds__(512,1) void av_mma_kernel(
    const bf16* __restrict__ Phi, const bf16* __restrict__ Plo,
    const bf16* __restrict__ Vthi, const bf16* __restrict__ Vtlo,
    float* __restrict__ Qh)
{
    extern __shared__ __align__(16) bf16 sm[];
    const int tid = threadIdx.x;
    const int warp = tid >> 5, lane = tid & 31;
    const int wm = warp >> 2, wn = warp & 3;
    const int g = lane >> 2, t4 = lane & 3;
    const int bz = blockIdx.z;
    const int q0 = blockIdx.x * 128;

    const bf16* Ap[2] = { Phi + ((size_t)bz*NSEQ + q0)*NSEQ,
                          Plo + ((size_t)bz*NSEQ + q0)*NSEQ };
    const bf16* Bp[2] = { Vthi + (size_t)bz*D_*NSEQ,
                          Vtlo + (size_t)bz*D_*NSEQ };

    float acc[2][8][4] = {};

    for (int kc = 0; kc < NSEQ; kc += 32) {
        for (int i = tid; i < 3072; i += 512) {
            if (i < 1024) {
                int mat = i >> 9, rem = i & 511, row = rem >> 2, q = rem & 3;
                *(uint4*)SMA(mat, row, q*8) =
                    *(const uint4*)(Ap[mat] + (size_t)row*NSEQ + kc + q*8);
            } else {
                int j = i - 1024;
                int mat = j >> 10, rem = j & 1023, row = rem >> 2, q = rem & 3;
                *(uint4*)SMB(mat, row, q*8) =
                    *(const uint4*)(Bp[mat] + (size_t)row*NSEQ + kc + q*8);
            }
        }
        __syncthreads();
        #pragma unroll
        for (int ks = 0; ks < 2; ks++) {
            const int kb = ks*16 + 2*t4;
            unsigned bF[2][8][2];
            #pragma unroll
            for (int mat = 0; mat < 2; mat++)
                #pragma unroll
                for (int nt = 0; nt < 8; nt++) {
                    int n = wn*64 + nt*8 + g;
                    bF[mat][nt][0] = *(const unsigned*)SMB(mat, n, kb);
                    bF[mat][nt][1] = *(const unsigned*)SMB(mat, n, kb+8);
                }
            #pragma unroll
            for (int mt = 0; mt < 2; mt++) {
                int r = wm*32 + mt*16 + g;
                unsigned a[4];
                a[0]=*(const unsigned*)SMA(0,r,kb);   a[1]=*(const unsigned*)SMA(0,r+8,kb);
                a[2]=*(const unsigned*)SMA(0,r,kb+8); a[3]=*(const unsigned*)SMA(0,r+8,kb+8);
                #pragma unroll
                for (int nt=0; nt<8; nt++) {
                    mma16816(acc[mt][nt], a, bF[0][nt]);
                    mma16816(acc[mt][nt], a, bF[1][nt]);
                }
                a[0]=*(const unsigned*)SMA(1,r,kb);   a[1]=*(const unsigned*)SMA(1,r+8,kb);
                a[2]=*(const unsigned*)SMA(1,r,kb+8); a[3]=*(const unsigned*)SMA(1,r+8,kb+8);
                #pragma unroll
                for (int nt=0; nt<8; nt++) mma16816(acc[mt][nt], a, bF[0][nt]);
            }
        }
        __syncthreads();
    }

    float* ob = Qh + ((size_t)bz*NSEQ + q0)*D_;
    #pragma unroll
    for (int mt=0; mt<2; mt++)
        #pragma unroll
        for (int nt=0; nt<8; nt++) {
            int r = wm*32 + mt*16 + g;
            int c = wn*64 + nt*8 + 2*t4;
            float2 v0 = { acc[mt][nt][0], acc[mt][nt][1] };
            float2 v1 = { acc[mt][nt][2], acc[mt][nt][3] };
            *(float2*)(ob + (size_t)r*D_ + c)     = v0;
            *(float2*)(ob + (size_t)(r+8)*D_ + c) = v1;
        }
}

// ===================== fused gate epilogue ==================================
__device__ __forceinline__ void blockSum2_128(float& a, float& b) {
    __shared__ float sh[8];
    #pragma unroll
    for (int o=16;o>0;o>>=1) {
        a += __shfl_xor_sync(0xffffffffu, a, o);
        b += __shfl_xor_sync(0xffffffffu, b, o);
    }
    if ((threadIdx.x & 31)==0) { sh[threadIdx.x>>5]=a; sh[4+(threadIdx.x>>5)]=b; }
    __syncthreads();
    a = sh[0]+sh[1]+sh[2]+sh[3];
    b = sh[4]+sh[5]+sh[6]+sh[7];
    __syncthreads();
}

__global__ __launch_bounds__(128) void epilogue_kernel(
    const float* __restrict__ Qg, const float* __restrict__ Qhg,
    const float* __restrict__ W1, const float* __restrict__ b1,
    const float* __restrict__ W2, const float* __restrict__ b2,
    const float* __restrict__ W3, const float* __restrict__ b3,
    const float* __restrict__ Wc, const float* __restrict__ bc,
    const float* __restrict__ Wf, const float* __restrict__ bf,
    const float* __restrict__ gg, const float* __restrict__ gb,
    const float* __restrict__ eg, const float* __restrict__ eb,
    float* __restrict__ out)
{
    __shared__ float Qs[EROWS][D_];
    __shared__ float Qh[EROWS][D_];
    __shared__ float ges[EROWS][NOUT];
    int j = threadIdx.x;
    size_t row0 = (size_t)blockIdx.x * EROWS;

    {
        const float4* s1 = (const float4*)(Qg  + row0*D_);
        const float4* s2 = (const float4*)(Qhg + row0*D_);
        float4* dQ = (float4*)&Qs[0][0];
        float4* dH = (float4*)&Qh[0][0];
        for (int t=j; t<EROWS*D_/4; t+=128) { dQ[t]=s1[t]; dH[t]=s2[t]; }
    }
    __syncthreads();

    float acc1[EROWS]={}, acc2[EROWS]={}, acc3[EROWS]={}, accF[EROWS]={};
    for (int c=0; c<D_; c+=4) {
        float w1v[4], w2v[4], w3v[4], wfv[4];
        #pragma unroll
        for (int u=0;u<4;u++) {
            w1v[u]=W1[(c+u)*NOUT+j]; w2v[u]=W2[(c+u)*NOUT+j];
            w3v[u]=W3[(c+u)*NOUT+j]; wfv[u]=Wf[(c+u)*NOUT+j];
        }
        #pragma unroll
        for (int r=0;r<EROWS;r++) {
            float4 q = *(const float4*)&Qs[r][c];
            float4 h = *(const float4*)&Qh[r][c];
            acc1[r] += q.x*w1v[0]+q.y*w1v[1]+q.z*w1v[2]+q.w*w1v[3];
            accF[r] += q.x*wfv[0]+q.y*wfv[1]+q.z*wfv[2]+q.w*wfv[3];
            acc2[r] += h.x*w2v[0]+h.y*w2v[1]+h.z*w2v[2]+h.w*w2v[3];
            acc3[r] += h.x*w3v[0]+h.y*w3v[1]+h.z*w3v[2]+h.w*w3v[3];
        }
    }

    float bb1=b1[j], bb2=b2[j], bb3=b3[j], bbf=bf[j], bbc=bc[j];
    float ggj=gg[j], gbj=gb[j], egj=eg[j], ebj=eb[j];

    #pragma unroll 1
    for (int r=0;r<EROWS;r++) {
        float gin = fmaxf(fmaxf(acc1[r]+bb1,0.f) + fmaxf(acc2[r]+bb2,0.f), 0.f);
        float ein = fmaxf(acc3[r]+bb3, 0.f);
        float s1 = gin, s2 = gin*gin;
        blockSum2_128(s1, s2);
        float mu  = s1*(1.0f/NOUT);
        float var = s2*(1.0f/NOUT) - mu*mu;
        float G = (gin-mu)*rsqrtf(var+EPS)*ggj + gbj;
        s1 = ein; s2 = ein*ein;
        blockSum2_128(s1, s2);
        mu  = s1*(1.0f/NOUT);
        var = s2*(1.0f/NOUT) - mu*mu;
        float E = (ein-mu)*rsqrtf(var+EPS)*egj + ebj;
        ges[r][j] = G*E;
        accF[r] = fmaxf(accF[r]+bbf, 0.f);
    }
    __syncthreads();

    float accC[EROWS]={};
    for (int k=0;k<NOUT;k++) {
        float wc = Wc[k*NOUT+j];
        #pragma unroll
        for (int r=0;r<EROWS;r++) accC[r] += ges[r][k]*wc;
    }
    #pragma unroll
    for (int r=0;r<EROWS;r++)
        out[(row0+r)*NOUT + j] = accF[r] + fmaxf(accC[r]+bbc, 0.f);
}

// ============================================================================
extern "C" void kernel_launch(void* const* d_in, const int* in_sizes, int n_in,
                              void* d_out, int out_size)
{
    const float* x1 = (const float*)d_in[0];
    const float* x2 = (const float*)d_in[1];
    const float* W_q=(const float*)d_in[2];  const float* b_q=(const float*)d_in[3];
    const float* W_k=(const float*)d_in[4];  const float* b_k=(const float*)d_in[5];
    const float* W_v=(const float*)d_in[6];  const float* b_v=(const float*)d_in[7];
    const float* W1 =(const float*)d_in[8];  const float* b1 =(const float*)d_in[9];
    const float* W2 =(const float*)d_in[10]; const float* b2 =(const float*)d_in[11];
    const float* W3 =(const float*)d_in[12]; const float* b3 =(const float*)d_in[13];
    const float* gg =(const float*)d_in[14]; const float* gb =(const float*)d_in[15];
    const float* eg =(const float*)d_in[16]; const float* eb =(const float*)d_in[17];
    const float* Wc =(const float*)d_in[18]; const float* bc =(const float*)d_in[19];
    const float* Wf =(const float*)d_in[20]; const float* bf =(const float*)d_in[21];

    float* out     = (float*)d_out;
    float* outMain = out;
    float* attn    = out + (size_t)MTOT*NOUT;

    float *Q,*Qh;
    bf16 *Qhi,*Qlo,*tQhi,*tQlo,*Khi,*Klo,*tKhi,*tKlo,*Vthi,*Vtlo,*Phi,*Plo;
    cudaGetSymbolAddress((void**)&Q,   g_Q);
    cudaGetSymbolAddress((void**)&Qh,  g_Qh);
    cudaGetSymbolAddress((void**)&Qhi, g_Qhi);  cudaGetSymbolAddress((void**)&Qlo, g_Qlo);
    cudaGetSymbolAddress((void**)&tQhi,g_tQhi); cudaGetSymbolAddress((void**)&tQlo,g_tQlo);
    cudaGetSymbolAddress((void**)&Khi, g_Khi);  cudaGetSymbolAddress((void**)&Klo, g_Klo);
    cudaGetSymbolAddress((void**)&tKhi,g_tKhi); cudaGetSymbolAddress((void**)&tKlo,g_tKlo);
    cudaGetSymbolAddress((void**)&Vthi,g_Vthi); cudaGetSymbolAddress((void**)&Vtlo,g_Vtlo);
    cudaGetSymbolAddress((void**)&Phi, g_Phi);  cudaGetSymbolAddress((void**)&Plo, g_Plo);

    cudaFuncSetAttribute(scores_mma_kernel, cudaFuncAttributeMaxDynamicSharedMemorySize, 81920);
    cudaFuncSetAttribute(av_mma_kernel,     cudaFuncAttributeMaxDynamicSharedMemorySize, 61440);

    dim3 pg(D_/64, MTOT/64);
    proj_kernel<0><<<pg, 256>>>(x2, W_q, b_q, Q, Qhi, Qlo, tQhi, tQlo);
    proj_kernel<1><<<pg, 256>>>(x1, W_k, b_k, nullptr, Khi, Klo, tKhi, tKlo);
    proj_kernel<2><<<pg, 256>>>(x1, W_v, b_v, nullptr, Vthi, Vtlo, nullptr, nullptr);

    scores_mma_kernel<<<dim3(NSEQ/128, NSEQ/128, B_), 512, 81920>>>(
        Qhi, Qlo, tQhi, tQlo, Khi, Klo, tKhi, tKlo, attn);

    softmax_kernel<<<MTOT, 256>>>(attn, Phi, Plo);

    av_mma_kernel<<<dim3(NSEQ/128, 1, B_), 512, 61440>>>(Phi, Plo, Vthi, Vtlo, Qh);

    epilogue_kernel<<<MTOT/EROWS, 128>>>(Q, Qh, W1,b1, W2,b2, W3,b3,
                                         Wc,bc, Wf,bf, gg,gb, eg,eb, outMain);
}

// round 7
// speedup vs baseline: 2.5173x; 1.6643x over previous
#include <cuda_runtime.h>
#include <cuda_bf16.h>
#include <stdint.h>
#include <math.h>

#define B_    4
#define NSEQ  4096
#define MTOT  (B_*NSEQ)
#define D_    256
#define NOUT  128
#define EPS   1e-5f
#define EROWS 16

typedef __nv_bfloat16 bf16;

// ---- scratch (static device globals; no allocation allowed) ----
__device__ float g_Q [(size_t)MTOT*D_];
__device__ float g_Qh[(size_t)MTOT*D_];
__device__ bf16 g_Qhi [(size_t)MTOT*D_], g_Qlo [(size_t)MTOT*D_];
__device__ bf16 g_tQhi[(size_t)MTOT*D_], g_tQlo[(size_t)MTOT*D_];
__device__ bf16 g_Khi [(size_t)MTOT*D_], g_Klo [(size_t)MTOT*D_];
__device__ bf16 g_tKhi[(size_t)MTOT*D_], g_tKlo[(size_t)MTOT*D_];
__device__ bf16 g_Vthi[(size_t)MTOT*D_], g_Vtlo[(size_t)MTOT*D_];   // [B][D][NSEQ]
__device__ bf16 g_Phi [(size_t)B_*NSEQ*NSEQ], g_Plo[(size_t)B_*NSEQ*NSEQ];

__device__ __forceinline__ void split_bf16(float x, bf16& h, bf16& l) {
    h = __float2bfloat16(x);
    l = __float2bfloat16(x - __bfloat162float(h));
}

__device__ __forceinline__ uint32_t smem_u32(const void* p) {
    uint32_t a;
    asm("{ .reg .u64 t; cvta.to.shared.u64 t, %1; cvt.u32.u64 %0, t; }" : "=r"(a) : "l"(p));
    return a;
}

#define CP_ASYNC16(dst, src) \
    asm volatile("cp.async.cg.shared.global [%0], [%1], 16;" :: "r"(dst), "l"(src) : "memory")
#define CP_COMMIT() asm volatile("cp.async.commit_group;" ::: "memory")
#define CP_WAIT0()  asm volatile("cp.async.wait_group 0;" ::: "memory")

// bf16 m16n8k16 mma, fp32 accum
__device__ __forceinline__ void mma16816(float* d, const unsigned* a, const unsigned* b) {
    asm volatile(
        "mma.sync.aligned.m16n8k16.row.col.f32.bf16.bf16.f32 "
        "{%0,%1,%2,%3}, {%4,%5,%6,%7}, {%8,%9}, {%0,%1,%2,%3};\n"
        : "+f"(d[0]), "+f"(d[1]), "+f"(d[2]), "+f"(d[3])
        : "r"(a[0]), "r"(a[1]), "r"(a[2]), "r"(a[3]), "r"(b[0]), "r"(b[1]));
}

// ================= projection: C = X@W + b =================================
template<int MODE>
__global__ __launch_bounds__(256) void proj_kernel(
    const float* __restrict__ X, const float* __restrict__ W,
    const float* __restrict__ bias, float* __restrict__ Cf,
    bf16* __restrict__ H1, bf16* __restrict__ L1,
    bf16* __restrict__ H2, bf16* __restrict__ L2)
{
    const int BM=64, BN=64, BK=16;
    __shared__ float Xs[BK][BM];
    __shared__ float Ws[BK][BN];
    int tid = threadIdx.x;
    int tx = tid & 15, ty = tid >> 4;
    int row0 = blockIdx.y * BM;
    int col0 = blockIdx.x * BN;
    int lr = tid >> 2, lc4 = tid & 3;
    int wkr = tid >> 4, wc4 = tid & 15;
    float acc[4][4] = {};

    for (int k0 = 0; k0 < D_; k0 += BK) {
        float4 v = *(const float4*)(X + (size_t)(row0+lr)*D_ + k0 + lc4*4);
        Xs[lc4*4+0][lr]=v.x; Xs[lc4*4+1][lr]=v.y; Xs[lc4*4+2][lr]=v.z; Xs[lc4*4+3][lr]=v.w;
        *(float4*)&Ws[wkr][wc4*4] = *(const float4*)(W + (size_t)(k0+wkr)*D_ + col0 + wc4*4);
        __syncthreads();
        #pragma unroll
        for (int kk=0; kk<BK; kk++) {
            float4 a4 = *(const float4*)&Xs[kk][ty*4];
            float4 w4 = *(const float4*)&Ws[kk][tx*4];
            float av[4]={a4.x,a4.y,a4.z,a4.w}, wv[4]={w4.x,w4.y,w4.z,w4.w};
            #pragma unroll
            for (int i=0;i<4;i++)
                #pragma unroll
                for (int j=0;j<4;j++) acc[i][j] += av[i]*wv[j];
        }
        __syncthreads();
    }
    #pragma unroll
    for (int i=0;i<4;i++) {
        size_t r = row0 + ty*4 + i;
        #pragma unroll
        for (int j=0;j<4;j++) {
            int cix = col0 + tx*4 + j;
            float val = acc[i][j] + bias[cix];
            if (MODE == 0) {
                Cf[r*D_ + cix] = val;
                bf16 h,l; split_bf16(val, h, l);
                H1[r*D_+cix]=h; L1[r*D_+cix]=l;
                float t = tanhf(val);
                split_bf16(t, h, l);
                H2[r*D_+cix]=h; L2[r*D_+cix]=l;
            } else if (MODE == 1) {
                bf16 h,l; split_bf16(val, h, l);
                H1[r*D_+cix]=h; L1[r*D_+cix]=l;
                float t = tanhf(val);
                split_bf16(t, h, l);
                H2[r*D_+cix]=h; L2[r*D_+cix]=l;
            } else {
                int b = (int)(r >> 12), s = (int)(r & 4095);
                size_t ti = ((size_t)b*D_ + cix)*NSEQ + s;
                bf16 h,l; split_bf16(val, h, l);
                H1[ti]=h; L1[ti]=l;
            }
        }
    }
}

// ====== dual-GEMM scores via bf16 mma + cp.async double buffer ==============
#define SC_STAGE_EL 40960
#define SMMs(smp,mat,row,col) ((smp) + (mat)*5120 + (row)*40 + (col))

__device__ __forceinline__ void sc_load_chunk(
    const bf16* const* Am, const bf16* const* Bm, uint32_t stage_b, int kc, int tid)
{
    #pragma unroll
    for (int t=0;t<8;t++) {
        int i = tid + t*512;
        const bf16* src; uint32_t dst;
        if (i < 2048) {
            int m = i >> 9, rem = i & 511, row = rem >> 2, c8 = rem & 3;
            src = Am[m] + (size_t)row*D_ + kc + c8*8;
            dst = stage_b + (uint32_t)(m*5120 + row*40 + c8*8)*2u;
        } else {
            int j = i - 2048;
            int m = j >> 9, rem = j & 511, row = rem >> 2, c8 = rem & 3;
            src = Bm[m] + (size_t)row*D_ + kc + c8*8;
            dst = stage_b + (uint32_t)(20480 + m*5120 + row*40 + c8*8)*2u;
        }
        CP_ASYNC16(dst, src);
    }
}

__global__ __launch_bounds__(512,1) void scores_mma_kernel(
    const bf16* __restrict__ Qhi, const bf16* __restrict__ Qlo,
    const bf16* __restrict__ tQhi,const bf16* __restrict__ tQlo,
    const bf16* __restrict__ Khi, const bf16* __restrict__ Klo,
    const bf16* __restrict__ tKhi,const bf16* __restrict__ tKlo,
    float* __restrict__ attn)
{
    extern __shared__ __align__(16) bf16 sm[];
    const uint32_t smb = smem_u32(sm);
    const int tid = threadIdx.x;
    const int warp = tid >> 5, lane = tid & 31;
    const int wm = warp >> 2, wn = warp & 3;
    const int g = lane >> 2, t4 = lane & 3;
    const int bz = blockIdx.z;
    const int q0 = blockIdx.y * 128, c0 = blockIdx.x * 128;

    const bf16* Am[4] = { Qhi + ((size_t)bz*NSEQ + q0)*D_,  Qlo + ((size_t)bz*NSEQ + q0)*D_,
                          tQhi + ((size_t)bz*NSEQ + q0)*D_, tQlo + ((size_t)bz*NSEQ + q0)*D_ };
    const bf16* Bm[4] = { Khi + ((size_t)bz*NSEQ + c0)*D_,  Klo + ((size_t)bz*NSEQ + c0)*D_,
                          tKhi + ((size_t)bz*NSEQ + c0)*D_, tKlo + ((size_t)bz*NSEQ + c0)*D_ };

    float accQ[2][4][4] = {};
    float accT[2][4][4] = {};

    sc_load_chunk(Am, Bm, smb, 0, tid);
    CP_COMMIT();

    for (int ch = 0; ch < 8; ch++) {
        bf16* smp = sm + (ch & 1) * SC_STAGE_EL;
        CP_WAIT0();
        __syncthreads();
        if (ch + 1 < 8) {
            sc_load_chunk(Am, Bm, smb + ((ch+1)&1) * (SC_STAGE_EL*2u), (ch+1)*32, tid);
            CP_COMMIT();
        }
        #pragma unroll
        for (int ks = 0; ks < 2; ks++) {
            const int kb = ks*16 + 2*t4;
            unsigned bF[4][4][2];
            #pragma unroll
            for (int mat = 0; mat < 4; mat++)
                #pragma unroll
                for (int nt = 0; nt < 4; nt++) {
                    int n = wn*32 + nt*8 + g;
                    bF[mat][nt][0] = *(const unsigned*)SMMs(smp, 4+mat, n, kb);
                    bF[mat][nt][1] = *(const unsigned*)SMMs(smp, 4+mat, n, kb+8);
                }
            #pragma unroll
            for (int mt = 0; mt < 2; mt++) {
                int r = wm*32 + mt*16 + g;
                unsigned a[4];
                // Q hi
                a[0]=*(const unsigned*)SMMs(smp,0,r,kb);   a[1]=*(const unsigned*)SMMs(smp,0,r+8,kb);
                a[2]=*(const unsigned*)SMMs(smp,0,r,kb+8); a[3]=*(const unsigned*)SMMs(smp,0,r+8,kb+8);
                #pragma unroll
                for (int nt=0; nt<4; nt++) {
                    mma16816(accQ[mt][nt], a, bF[0][nt]);
                    mma16816(accQ[mt][nt], a, bF[1][nt]);
                }
                // Q lo
                a[0]=*(const unsigned*)SMMs(smp,1,r,kb);   a[1]=*(const unsigned*)SMMs(smp,1,r+8,kb);
                a[2]=*(const unsigned*)SMMs(smp,1,r,kb+8); a[3]=*(const unsigned*)SMMs(smp,1,r+8,kb+8);
                #pragma unroll
                for (int nt=0; nt<4; nt++) mma16816(accQ[mt][nt], a, bF[0][nt]);
                // tanh hi
                a[0]=*(const unsigned*)SMMs(smp,2,r,kb);   a[1]=*(const unsigned*)SMMs(smp,2,r+8,kb);
                a[2]=*(const unsigned*)SMMs(smp,2,r,kb+8); a[3]=*(const unsigned*)SMMs(smp,2,r+8,kb+8);
                #pragma unroll
                for (int nt=0; nt<4; nt++) {
                    mma16816(accT[mt][nt], a, bF[2][nt]);
                    mma16816(accT[mt][nt], a, bF[3][nt]);
                }
                // tanh lo
                a[0]=*(const unsigned*)SMMs(smp,3,r,kb);   a[1]=*(const unsigned*)SMMs(smp,3,r+8,kb);
                a[2]=*(const unsigned*)SMMs(smp,3,r,kb+8); a[3]=*(const unsigned*)SMMs(smp,3,r+8,kb+8);
                #pragma unroll
                for (int nt=0; nt<4; nt++) mma16816(accT[mt][nt], a, bF[2][nt]);
            }
        }
        __syncthreads();
    }

    float* ob = attn + (size_t)bz*NSEQ*NSEQ;
    #pragma unroll
    for (int mt=0; mt<2; mt++)
        #pragma unroll
        for (int nt=0; nt<4; nt++) {
            int r = q0 + wm*32 + mt*16 + g;
            int c = c0 + wn*32 + nt*8 + 2*t4;
            const float* aq = accQ[mt][nt];
            const float* at = accT[mt][nt];
            float2 v0 = { aq[0]*(at[0]+1.0f)*0.03125f, aq[1]*(at[1]+1.0f)*0.03125f };
            float2 v1 = { aq[2]*(at[2]+1.0f)*0.03125f, aq[3]*(at[3]+1.0f)*0.03125f };
            *(float2*)(ob + (size_t)r*NSEQ + c)     = v0;
            *(float2*)(ob + (size_t)(r+8)*NSEQ + c) = v1;
        }
}

// ========================= Qhat = attn @ V (mma + cp.async) =================
#define AV_STAGE_EL 30720
#define AV_NCHUNK  (NSEQ/32)   // 128 chunks — full K=4096 reduction
#define SMAs(smp,mat,row,col) ((smp) + (mat)*5120 + (row)*40 + (col))
#define SMBs(smp,mat,row,col) ((smp) + 10240 + (mat)*10240 + (row)*40 + (col))

__device__ __forceinline__ void av_load_chunk(
    const bf16* const* Am, const bf16* const* Bm, uint32_t stage_b, int kc, int tid)
{
    #pragma unroll
    for (int t=0;t<6;t++) {
        int i = tid + t*512;
        const bf16* src; uint32_t dst;
        if (i < 1024) {
            int m = i >> 9, rem = i & 511, row = rem >> 2, c8 = rem & 3;
            src = Am[m] + (size_t)row*NSEQ + kc + c8*8;
            dst = stage_b + (uint32_t)(m*5120 + row*40 + c8*8)*2u;
        } else {
            int j = i - 1024;
            int m = j >> 10, rem = j & 1023, row = rem >> 2, c8 = rem & 3;
            src = Bm[m] + (size_t)row*NSEQ + kc + c8*8;
            dst = stage_b + (uint32_t)(10240 + m*10240 + row*40 + c8*8)*2u;
        }
        CP_ASYNC16(dst, src);
    }
}

__global__ __launch_bounds__(512,1) void av_mma_kernel(
    const bf16* __restrict__ Phi, const bf16* __restrict__ Plo,
    const bf16* __restrict__ Vthi, const bf16* __restrict__ Vtlo,
    float* __restrict__ Qh)
{
    extern __shared__ __align__(16) bf16 sm[];
    const uint32_t smb = smem_u32(sm);
    const int tid = threadIdx.x;
    const int warp = tid >> 5, lane = tid & 31;
    const int wm = warp >> 2, wn = warp & 3;
    const int g = lane >> 2, t4 = lane & 3;
    const int bz = blockIdx.z;
    const int q0 = blockIdx.x * 128;

    const bf16* Am[2] = { Phi + ((size_t)bz*NSEQ + q0)*NSEQ,
                          Plo + ((size_t)bz*NSEQ + q0)*NSEQ };
    const bf16* Bm[2] = { Vthi + (size_t)bz*D_*NSEQ,
                          Vtlo + (size_t)bz*D_*NSEQ };

    float acc[2][8][4] = {};

    av_load_chunk(Am, Bm, smb, 0, tid);
    CP_COMMIT();

    for (int ch = 0; ch < AV_NCHUNK; ch++) {
        bf16* smp = sm + (ch & 1) * AV_STAGE_EL;
        CP_WAIT0();
        __syncthreads();
        if (ch + 1 < AV_NCHUNK) {
            av_load_chunk(Am, Bm, smb + ((ch+1)&1) * (AV_STAGE_EL*2u), (ch+1)*32, tid);
            CP_COMMIT();
        }
        #pragma unroll
        for (int ks = 0; ks < 2; ks++) {
            const int kb = ks*16 + 2*t4;
            unsigned bF[2][8][2];
            #pragma unroll
            for (int mat = 0; mat < 2; mat++)
                #pragma unroll
                for (int nt = 0; nt < 8; nt++) {
                    int n = wn*64 + nt*8 + g;
                    bF[mat][nt][0] = *(const unsigned*)SMBs(smp, mat, n, kb);
                    bF[mat][nt][1] = *(const unsigned*)SMBs(smp, mat, n, kb+8);
                }
            #pragma unroll
            for (int mt = 0; mt < 2; mt++) {
                int r = wm*32 + mt*16 + g;
                unsigned a[4];
                a[0]=*(const unsigned*)SMAs(smp,0,r,kb);   a[1]=*(const unsigned*)SMAs(smp,0,r+8,kb);
                a[2]=*(const unsigned*)SMAs(smp,0,r,kb+8); a[3]=*(const unsigned*)SMAs(smp,0,r+8,kb+8);
                #pragma unroll
                for (int nt=0; nt<8; nt++) {
                    mma16816(acc[mt][nt], a, bF[0][nt]);
                    mma16816(acc[mt][nt], a, bF[1][nt]);
                }
                a[0]=*(const unsigned*)SMAs(smp,1,r,kb);   a[1]=*(const unsigned*)SMAs(smp,1,r+8,kb);
                a[2]=*(const unsigned*)SMAs(smp,1,r,kb+8); a[3]=*(const unsigned*)SMAs(smp,1,r+8,kb+8);
                #pragma unroll
                for (int nt=0; nt<8; nt++) mma16816(acc[mt][nt], a, bF[0][nt]);
            }
        }
        __syncthreads();
    }

    float* ob = Qh + ((size_t)bz*NSEQ + q0)*D_;
    #pragma unroll
    for (int mt=0; mt<2; mt++)
        #pragma unroll
        for (int nt=0; nt<8; nt++) {
            int r = wm*32 + mt*16 + g;
            int c = wn*64 + nt*8 + 2*t4;
            float2 v0 = { acc[mt][nt][0], acc[mt][nt][1] };
            float2 v1 = { acc[mt][nt][2], acc[mt][nt][3] };
            *(float2*)(ob + (size_t)r*D_ + c)     = v0;
            *(float2*)(ob + (size_t)(r+8)*D_ + c) = v1;
        }
}

// ======================= in-place row softmax (4096) + hi/lo ================
__device__ __forceinline__ float blockMax256(float v) {
    __shared__ float sh[8];
    #pragma unroll
    for (int o=16;o>0;o>>=1) v = fmaxf(v, __shfl_xor_sync(0xffffffffu, v, o));
    if ((threadIdx.x & 31)==0) sh[threadIdx.x>>5] = v;
    __syncthreads();
    float m = sh[0];
    #pragma unroll
    for (int w=1;w<8;w++) m = fmaxf(m, sh[w]);
    __syncthreads();
    return m;
}
__device__ __forceinline__ float blockSum256(float v) {
    __shared__ float sh[8];
    #pragma unroll
    for (int o=16;o>0;o>>=1) v += __shfl_xor_sync(0xffffffffu, v, o);
    if ((threadIdx.x & 31)==0) sh[threadIdx.x>>5] = v;
    __syncthreads();
    float s = sh[0];
    #pragma unroll
    for (int w=1;w<8;w++) s += sh[w];
    __syncthreads();
    return s;
}
__global__ __launch_bounds__(256) void softmax_kernel(
    float* __restrict__ attn, bf16* __restrict__ Phi, bf16* __restrict__ Plo)
{
    size_t rb = (size_t)blockIdx.x * NSEQ;
    float4* p = (float4*)(attn + rb);
    int tid = threadIdx.x;
    float4 v[4];
    #pragma unroll
    for (int t=0;t<4;t++) v[t] = p[tid + 256*t];
    float m = -1e30f;
    #pragma unroll
    for (int t=0;t<4;t++)
        m = fmaxf(m, fmaxf(fmaxf(v[t].x, v[t].y), fmaxf(v[t].z, v[t].w)));
    m = blockMax256(m);
    float s = 0.f;
    #pragma unroll
    for (int t=0;t<4;t++) {
        v[t].x = __expf(v[t].x - m); v[t].y = __expf(v[t].y - m);
        v[t].z = __expf(v[t].z - m); v[t].w = __expf(v[t].w - m);
        s += v[t].x + v[t].y + v[t].z + v[t].w;
    }
    s = blockSum256(s);
    float inv = 1.0f / s;
    #pragma unroll
    for (int t=0;t<4;t++) {
        v[t].x *= inv; v[t].y *= inv; v[t].z *= inv; v[t].w *= inv;
        p[tid + 256*t] = v[t];
        int idx = (tid + 256*t)*4;
        float f[4] = {v[t].x, v[t].y, v[t].z, v[t].w};
        bf16 h[4], l[4];
        #pragma unroll
        for (int u=0;u<4;u++) split_bf16(f[u], h[u], l[u]);
        __nv_bfloat162 h01; h01.x=h[0]; h01.y=h[1];
        __nv_bfloat162 h23; h23.x=h[2]; h23.y=h[3];
        __nv_bfloat162 l01; l01.x=l[0]; l01.y=l[1];
        __nv_bfloat162 l23; l23.x=l[2]; l23.y=l[3];
        __nv_bfloat162* hp = (__nv_bfloat162*)(Phi + rb + idx);
        __nv_bfloat162* lp = (__nv_bfloat162*)(Plo + rb + idx);
        hp[0]=h01; hp[1]=h23; lp[0]=l01; lp[1]=l23;
    }
}

// ===================== fused gate epilogue ==================================
__device__ __forceinline__ void blockSum2_128(float& a, float& b) {
    __shared__ float sh[8];
    #pragma unroll
    for (int o=16;o>0;o>>=1) {
        a += __shfl_xor_sync(0xffffffffu, a, o);
        b += __shfl_xor_sync(0xffffffffu, b, o);
    }
    if ((threadIdx.x & 31)==0) { sh[threadIdx.x>>5]=a; sh[4+(threadIdx.x>>5)]=b; }
    __syncthreads();
    a = sh[0]+sh[1]+sh[2]+sh[3];
    b = sh[4]+sh[5]+sh[6]+sh[7];
    __syncthreads();
}

__global__ __launch_bounds__(128) void epilogue_kernel(
    const float* __restrict__ Qg, const float* __restrict__ Qhg,
    const float* __restrict__ W1, const float* __restrict__ b1,
    const float* __restrict__ W2, const float* __restrict__ b2,
    const float* __restrict__ W3, const float* __restrict__ b3,
    const float* __restrict__ Wc, const float* __restrict__ bc,
    const float* __restrict__ Wf, const float* __restrict__ bf,
    const float* __restrict__ gg, const float* __restrict__ gb,
    const float* __restrict__ eg, const float* __restrict__ eb,
    float* __restrict__ out)
{
    __shared__ float Qs[EROWS][D_];
    __shared__ float Qh[EROWS][D_];
    __shared__ float ges[EROWS][NOUT];
    int j = threadIdx.x;
    size_t row0 = (size_t)blockIdx.x * EROWS;

    {
        const float4* s1 = (const float4*)(Qg  + row0*D_);
        const float4* s2 = (const float4*)(Qhg + row0*D_);
        float4* dQ = (float4*)&Qs[0][0];
        float4* dH = (float4*)&Qh[0][0];
        for (int t=j; t<EROWS*D_/4; t+=128) { dQ[t]=s1[t]; dH[t]=s2[t]; }
    }
    __syncthreads();

    float acc1[EROWS]={}, acc2[EROWS]={}, acc3[EROWS]={}, accF[EROWS]={};
    for (int c=0; c<D_; c+=4) {
        float w1v[4], w2v[4], w3v[4], wfv[4];
        #pragma unroll
        for (int u=0;u<4;u++) {
            w1v[u]=W1[(c+u)*NOUT+j]; w2v[u]=W2[(c+u)*NOUT+j];
            w3v[u]=W3[(c+u)*NOUT+j]; wfv[u]=Wf[(c+u)*NOUT+j];
        }
        #pragma unroll
        for (int r=0;r<EROWS;r++) {
            float4 q = *(const float4*)&Qs[r][c];
            float4 h = *(const float4*)&Qh[r][c];
            acc1[r] += q.x*w1v[0]+q.y*w1v[1]+q.z*w1v[2]+q.w*w1v[3];
            accF[r] += q.x*wfv[0]+q.y*wfv[1]+q.z*wfv[2]+q.w*wfv[3];
            acc2[r] += h.x*w2v[0]+h.y*w2v[1]+h.z*w2v[2]+h.w*w2v[3];
            acc3[r] += h.x*w3v[0]+h.y*w3v[1]+h.z*w3v[2]+h.w*w3v[3];
        }
    }

    float bb1=b1[j], bb2=b2[j], bb3=b3[j], bbf=bf[j], bbc=bc[j];
    float ggj=gg[j], gbj=gb[j], egj=eg[j], ebj=eb[j];

    #pragma unroll 1
    for (int r=0;r<EROWS;r++) {
        float gin = fmaxf(fmaxf(acc1[r]+bb1,0.f) + fmaxf(acc2[r]+bb2,0.f), 0.f);
        float ein = fmaxf(acc3[r]+bb3, 0.f);
        float s1 = gin, s2 = gin*gin;
        blockSum2_128(s1, s2);
        float mu  = s1*(1.0f/NOUT);
        float var = s2*(1.0f/NOUT) - mu*mu;
        float G = (gin-mu)*rsqrtf(var+EPS)*ggj + gbj;
        s1 = ein; s2 = ein*ein;
        blockSum2_128(s1, s2);
        mu  = s1*(1.0f/NOUT);
        var = s2*(1.0f/NOUT) - mu*mu;
        float E = (ein-mu)*rsqrtf(var+EPS)*egj + ebj;
        ges[r][j] = G*E;
        accF[r] = fmaxf(accF[r]+bbf, 0.f);
    }
    __syncthreads();

    float accC[EROWS]={};
    for (int k=0;k<NOUT;k++) {
        float wc = Wc[k*NOUT+j];
        #pragma unroll
        for (int r=0;r<EROWS;r++) accC[r] += ges[r][k]*wc;
    }
    #pragma unroll
    for (int r=0;r<EROWS;r++)
        out[(row0+r)*NOUT + j] = accF[r] + fmaxf(accC[r]+bbc, 0.f);
}

// ============================================================================
extern "C" void kernel_launch(void* const* d_in, const int* in_sizes, int n_in,
                              void* d_out, int out_size)
{
    const float* x1 = (const float*)d_in[0];
    const float* x2 = (const float*)d_in[1];
    const float* W_q=(const float*)d_in[2];  const float* b_q=(const float*)d_in[3];
    const float* W_k=(const float*)d_in[4];  const float* b_k=(const float*)d_in[5];
    const float* W_v=(const float*)d_in[6];  const float* b_v=(const float*)d_in[7];
    const float* W1 =(const float*)d_in[8];  const float* b1 =(const float*)d_in[9];
    const float* W2 =(const float*)d_in[10]; const float* b2 =(const float*)d_in[11];
    const float* W3 =(const float*)d_in[12]; const float* b3 =(const float*)d_in[13];
    const float* gg =(const float*)d_in[14]; const float* gb =(const float*)d_in[15];
    const float* eg =(const float*)d_in[16]; const float* eb =(const float*)d_in[17];
    const float* Wc =(const float*)d_in[18]; const float* bc =(const float*)d_in[19];
    const float* Wf =(const float*)d_in[20]; const float* bf =(const float*)d_in[21];

    float* out     = (float*)d_out;
    float* outMain = out;
    float* attn    = out + (size_t)MTOT*NOUT;

    float *Q,*Qh;
    bf16 *Qhi,*Qlo,*tQhi,*tQlo,*Khi,*Klo,*tKhi,*tKlo,*Vthi,*Vtlo,*Phi,*Plo;
    cudaGetSymbolAddress((void**)&Q,   g_Q);
    cudaGetSymbolAddress((void**)&Qh,  g_Qh);
    cudaGetSymbolAddress((void**)&Qhi, g_Qhi);  cudaGetSymbolAddress((void**)&Qlo, g_Qlo);
    cudaGetSymbolAddress((void**)&tQhi,g_tQhi); cudaGetSymbolAddress((void**)&tQlo,g_tQlo);
    cudaGetSymbolAddress((void**)&Khi, g_Khi);  cudaGetSymbolAddress((void**)&Klo, g_Klo);
    cudaGetSymbolAddress((void**)&tKhi,g_tKhi); cudaGetSymbolAddress((void**)&tKlo,g_tKlo);
    cudaGetSymbolAddress((void**)&Vthi,g_Vthi); cudaGetSymbolAddress((void**)&Vtlo,g_Vtlo);
    cudaGetSymbolAddress((void**)&Phi, g_Phi);  cudaGetSymbolAddress((void**)&Plo, g_Plo);

    cudaFuncSetAttribute(scores_mma_kernel, cudaFuncAttributeMaxDynamicSharedMemorySize, 2*SC_STAGE_EL*2);
    cudaFuncSetAttribute(av_mma_kernel,     cudaFuncAttributeMaxDynamicSharedMemorySize, 2*AV_STAGE_EL*2);

    dim3 pg(D_/64, MTOT/64);
    proj_kernel<0><<<pg, 256>>>(x2, W_q, b_q, Q, Qhi, Qlo, tQhi, tQlo);
    proj_kernel<1><<<pg, 256>>>(x1, W_k, b_k, nullptr, Khi, Klo, tKhi, tKlo);
    proj_kernel<2><<<pg, 256>>>(x1, W_v, b_v, nullptr, Vthi, Vtlo, nullptr, nullptr);

    scores_mma_kernel<<<dim3(NSEQ/128, NSEQ/128, B_), 512, 2*SC_STAGE_EL*2>>>(
        Qhi, Qlo, tQhi, tQlo, Khi, Klo, tKhi, tKlo, attn);

    softmax_kernel<<<MTOT, 256>>>(attn, Phi, Plo);

    av_mma_kernel<<<dim3(NSEQ/128, 1, B_), 512, 2*AV_STAGE_EL*2>>>(Phi, Plo, Vthi, Vtlo, Qh);

    epilogue_kernel<<<MTOT/EROWS, 128>>>(Q, Qh, W1,b1, W2,b2, W3,b3,
                                         Wc,bc, Wf,bf, gg,gb, eg,eb, outMain);
}

// round 8
// speedup vs baseline: 2.5223x; 1.0020x over previous
#include <cuda_runtime.h>
#include <cuda_bf16.h>
#include <stdint.h>
#include <math.h>

#define B_    4
#define NSEQ  4096
#define MTOT  (B_*NSEQ)
#define D_    256
#define NOUT  128
#define EPS   1e-5f
#define EROWS 16

typedef __nv_bfloat16 bf16;

// ---- scratch (static device globals; no allocation allowed) ----
__device__ float g_Q [(size_t)MTOT*D_];
__device__ float g_Qh[(size_t)MTOT*D_];
__device__ bf16 g_Qhi [(size_t)MTOT*D_], g_Qlo [(size_t)MTOT*D_];
__device__ bf16 g_tQhi[(size_t)MTOT*D_], g_tQlo[(size_t)MTOT*D_];
__device__ bf16 g_Khi [(size_t)MTOT*D_], g_Klo [(size_t)MTOT*D_];
__device__ bf16 g_tKhi[(size_t)MTOT*D_], g_tKlo[(size_t)MTOT*D_];
__device__ bf16 g_Vthi[(size_t)MTOT*D_], g_Vtlo[(size_t)MTOT*D_];   // [B][D][NSEQ]
__device__ bf16 g_Phi [(size_t)B_*NSEQ*NSEQ], g_Plo[(size_t)B_*NSEQ*NSEQ];

__device__ __forceinline__ void split_bf16(float x, bf16& h, bf16& l) {
    h = __float2bfloat16(x);
    l = __float2bfloat16(x - __bfloat162float(h));
}

__device__ __forceinline__ uint32_t smem_u32(const void* p) {
    uint32_t a;
    asm("{ .reg .u64 t; cvta.to.shared.u64 t, %1; cvt.u32.u64 %0, t; }" : "=r"(a) : "l"(p));
    return a;
}

#define CP_ASYNC16(dst, src) \
    asm volatile("cp.async.cg.shared.global [%0], [%1], 16;" :: "r"(dst), "l"(src) : "memory")
#define CP_COMMIT() asm volatile("cp.async.commit_group;" ::: "memory")
#define CP_WAIT0()  asm volatile("cp.async.wait_group 0;" ::: "memory")

// bf16 m16n8k16 mma, fp32 accum
__device__ __forceinline__ void mma16816(float* d, const unsigned* a, const unsigned* b) {
    asm volatile(
        "mma.sync.aligned.m16n8k16.row.col.f32.bf16.bf16.f32 "
        "{%0,%1,%2,%3}, {%4,%5,%6,%7}, {%8,%9}, {%0,%1,%2,%3};\n"
        : "+f"(d[0]), "+f"(d[1]), "+f"(d[2]), "+f"(d[3])
        : "r"(a[0]), "r"(a[1]), "r"(a[2]), "r"(a[3]), "r"(b[0]), "r"(b[1]));
}

__device__ __forceinline__ void ldsm_x4(uint32_t addr, unsigned* r) {
    asm volatile("ldmatrix.sync.aligned.m8n8.x4.shared.b16 {%0,%1,%2,%3}, [%4];"
        : "=r"(r[0]), "=r"(r[1]), "=r"(r[2]), "=r"(r[3]) : "r"(addr));
}

// ================= projection: C = X@W + b =================================
template<int MODE>
__global__ __launch_bounds__(256) void proj_kernel(
    const float* __restrict__ X, const float* __restrict__ W,
    const float* __restrict__ bias, float* __restrict__ Cf,
    bf16* __restrict__ H1, bf16* __restrict__ L1,
    bf16* __restrict__ H2, bf16* __restrict__ L2)
{
    const int BM=64, BN=64, BK=16;
    __shared__ float Xs[BK][BM];
    __shared__ float Ws[BK][BN];
    int tid = threadIdx.x;
    int tx = tid & 15, ty = tid >> 4;
    int row0 = blockIdx.y * BM;
    int col0 = blockIdx.x * BN;
    int lr = tid >> 2, lc4 = tid & 3;
    int wkr = tid >> 4, wc4 = tid & 15;
    float acc[4][4] = {};

    for (int k0 = 0; k0 < D_; k0 += BK) {
        float4 v = *(const float4*)(X + (size_t)(row0+lr)*D_ + k0 + lc4*4);
        Xs[lc4*4+0][lr]=v.x; Xs[lc4*4+1][lr]=v.y; Xs[lc4*4+2][lr]=v.z; Xs[lc4*4+3][lr]=v.w;
        *(float4*)&Ws[wkr][wc4*4] = *(const float4*)(W + (size_t)(k0+wkr)*D_ + col0 + wc4*4);
        __syncthreads();
        #pragma unroll
        for (int kk=0; kk<BK; kk++) {
            float4 a4 = *(const float4*)&Xs[kk][ty*4];
            float4 w4 = *(const float4*)&Ws[kk][tx*4];
            float av[4]={a4.x,a4.y,a4.z,a4.w}, wv[4]={w4.x,w4.y,w4.z,w4.w};
            #pragma unroll
            for (int i=0;i<4;i++)
                #pragma unroll
                for (int j=0;j<4;j++) acc[i][j] += av[i]*wv[j];
        }
        __syncthreads();
    }
    #pragma unroll
    for (int i=0;i<4;i++) {
        size_t r = row0 + ty*4 + i;
        #pragma unroll
        for (int j=0;j<4;j++) {
            int cix = col0 + tx*4 + j;
            float val = acc[i][j] + bias[cix];
            if (MODE == 0) {
                Cf[r*D_ + cix] = val;
                bf16 h,l; split_bf16(val, h, l);
                H1[r*D_+cix]=h; L1[r*D_+cix]=l;
                float t = tanhf(val);
                split_bf16(t, h, l);
                H2[r*D_+cix]=h; L2[r*D_+cix]=l;
            } else if (MODE == 1) {
                bf16 h,l; split_bf16(val, h, l);
                H1[r*D_+cix]=h; L1[r*D_+cix]=l;
                float t = tanhf(val);
                split_bf16(t, h, l);
                H2[r*D_+cix]=h; L2[r*D_+cix]=l;
            } else {
                int b = (int)(r >> 12), s = (int)(r & 4095);
                size_t ti = ((size_t)b*D_ + cix)*NSEQ + s;
                bf16 h,l; split_bf16(val, h, l);
                H1[ti]=h; L1[ti]=l;
            }
        }
    }
}

// ====== dual-GEMM scores via bf16 mma + cp.async double buffer + ldmatrix ===
#define SC_STAGE_EL 40960

__device__ __forceinline__ void sc_load_chunk(
    const bf16* const* Am, const bf16* const* Bm, uint32_t stage_b, int kc, int tid)
{
    #pragma unroll
    for (int t=0;t<8;t++) {
        int i = tid + t*512;
        const bf16* src; uint32_t dst;
        if (i < 2048) {
            int m = i >> 9, rem = i & 511, row = rem >> 2, c8 = rem & 3;
            src = Am[m] + (size_t)row*D_ + kc + c8*8;
            dst = stage_b + (uint32_t)(m*5120 + row*40 + c8*8)*2u;
        } else {
            int j = i - 2048;
            int m = j >> 9, rem = j & 511, row = rem >> 2, c8 = rem & 3;
            src = Bm[m] + (size_t)row*D_ + kc + c8*8;
            dst = stage_b + (uint32_t)(20480 + m*5120 + row*40 + c8*8)*2u;
        }
        CP_ASYNC16(dst, src);
    }
}

__global__ __launch_bounds__(512,1) void scores_mma_kernel(
    const bf16* __restrict__ Qhi, const bf16* __restrict__ Qlo,
    const bf16* __restrict__ tQhi,const bf16* __restrict__ tQlo,
    const bf16* __restrict__ Khi, const bf16* __restrict__ Klo,
    const bf16* __restrict__ tKhi,const bf16* __restrict__ tKlo,
    float* __restrict__ attn)
{
    extern __shared__ __align__(16) bf16 sm[];
    const uint32_t smb = smem_u32(sm);
    const int tid = threadIdx.x;
    const int warp = tid >> 5, lane = tid & 31;
    const int wm = warp >> 2, wn = warp & 3;
    const int g = lane >> 2, t4 = lane & 3;
    const int m3 = lane >> 3, rr = lane & 7;
    const int aRowOff = ((m3 & 1) << 3) + rr, aColOff = (m3 >> 1) << 3;
    const int bRowOff = ((m3 >> 1) << 3) + rr, bColOff = (m3 & 1) << 3;
    const int bz = blockIdx.z;
    const int q0 = blockIdx.y * 128, c0 = blockIdx.x * 128;

    const bf16* Am[4] = { Qhi + ((size_t)bz*NSEQ + q0)*D_,  Qlo + ((size_t)bz*NSEQ + q0)*D_,
                          tQhi + ((size_t)bz*NSEQ + q0)*D_, tQlo + ((size_t)bz*NSEQ + q0)*D_ };
    const bf16* Bm[4] = { Khi + ((size_t)bz*NSEQ + c0)*D_,  Klo + ((size_t)bz*NSEQ + c0)*D_,
                          tKhi + ((size_t)bz*NSEQ + c0)*D_, tKlo + ((size_t)bz*NSEQ + c0)*D_ };

    float accQ[2][4][4] = {};
    float accT[2][4][4] = {};

    sc_load_chunk(Am, Bm, smb, 0, tid);
    CP_COMMIT();

    for (int ch = 0; ch < 8; ch++) {
        uint32_t sbase = smb + (uint32_t)(ch & 1) * (SC_STAGE_EL*2u);
        CP_WAIT0();
        __syncthreads();
        if (ch + 1 < 8) {
            sc_load_chunk(Am, Bm, smb + (uint32_t)((ch+1)&1) * (SC_STAGE_EL*2u), (ch+1)*32, tid);
            CP_COMMIT();
        }
        #pragma unroll
        for (int ks = 0; ks < 2; ks++) {
            const int kb0 = ks*16;
            // B fragments via ldmatrix.x4 (mats: (n0,k0),(n0,k8),(n8,k0),(n8,k8))
            unsigned bF[4][4][2];
            #pragma unroll
            for (int mat = 0; mat < 4; mat++)
                #pragma unroll
                for (int p = 0; p < 2; p++) {
                    int N0 = wn*32 + p*16;
                    uint32_t addr = sbase + (uint32_t)((4+mat)*5120 + (N0 + bRowOff)*40 + kb0 + bColOff)*2u;
                    unsigned r[4]; ldsm_x4(addr, r);
                    bF[mat][2*p  ][0]=r[0]; bF[mat][2*p  ][1]=r[1];
                    bF[mat][2*p+1][0]=r[2]; bF[mat][2*p+1][1]=r[3];
                }
            #pragma unroll
            for (int mt = 0; mt < 2; mt++) {
                int R = wm*32 + mt*16;
                unsigned a0[4], a1[4], a2[4], a3[4];
                uint32_t abase = sbase + (uint32_t)((R + aRowOff)*40 + kb0 + aColOff)*2u;
                ldsm_x4(abase,            a0);   // Qhi
                ldsm_x4(abase + 10240u,   a1);   // Qlo   (5120 el * 2B)
                ldsm_x4(abase + 20480u,   a2);   // tQhi
                ldsm_x4(abase + 30720u,   a3);   // tQlo
                #pragma unroll
                for (int nt=0; nt<4; nt++) {
                    mma16816(accQ[mt][nt], a0, bF[0][nt]);
                    mma16816(accQ[mt][nt], a0, bF[1][nt]);
                    mma16816(accQ[mt][nt], a1, bF[0][nt]);
                    mma16816(accT[mt][nt], a2, bF[2][nt]);
                    mma16816(accT[mt][nt], a2, bF[3][nt]);
                    mma16816(accT[mt][nt], a3, bF[2][nt]);
                }
            }
        }
        __syncthreads();
    }

    float* ob = attn + (size_t)bz*NSEQ*NSEQ;
    #pragma unroll
    for (int mt=0; mt<2; mt++)
        #pragma unroll
        for (int nt=0; nt<4; nt++) {
            int r = q0 + wm*32 + mt*16 + g;
            int c = c0 + wn*32 + nt*8 + 2*t4;
            const float* aq = accQ[mt][nt];
            const float* at = accT[mt][nt];
            float2 v0 = { aq[0]*(at[0]+1.0f)*0.03125f, aq[1]*(at[1]+1.0f)*0.03125f };
            float2 v1 = { aq[2]*(at[2]+1.0f)*0.03125f, aq[3]*(at[3]+1.0f)*0.03125f };
            *(float2*)(ob + (size_t)r*NSEQ + c)     = v0;
            *(float2*)(ob + (size_t)(r+8)*NSEQ + c) = v1;
        }
}

// ========================= Qhat = attn @ V (mma + cp.async + ldmatrix) ======
#define AV_STAGE_EL 30720
#define AV_NCHUNK  (NSEQ/32)   // 128 chunks — full K=4096 reduction

__device__ __forceinline__ void av_load_chunk(
    const bf16* const* Am, const bf16* const* Bm, uint32_t stage_b, int kc, int tid)
{
    #pragma unroll
    for (int t=0;t<6;t++) {
        int i = tid + t*512;
        const bf16* src; uint32_t dst;
        if (i < 1024) {
            int m = i >> 9, rem = i & 511, row = rem >> 2, c8 = rem & 3;
            src = Am[m] + (size_t)row*NSEQ + kc + c8*8;
            dst = stage_b + (uint32_t)(m*5120 + row*40 + c8*8)*2u;
        } else {
            int j = i - 1024;
            int m = j >> 10, rem = j & 1023, row = rem >> 2, c8 = rem & 3;
            src = Bm[m] + (size_t)row*NSEQ + kc + c8*8;
            dst = stage_b + (uint32_t)(10240 + m*10240 + row*40 + c8*8)*2u;
        }
        CP_ASYNC16(dst, src);
    }
}

__global__ __launch_bounds__(512,1) void av_mma_kernel(
    const bf16* __restrict__ Phi, const bf16* __restrict__ Plo,
    const bf16* __restrict__ Vthi, const bf16* __restrict__ Vtlo,
    float* __restrict__ Qh)
{
    extern __shared__ __align__(16) bf16 sm[];
    const uint32_t smb = smem_u32(sm);
    const int tid = threadIdx.x;
    const int warp = tid >> 5, lane = tid & 31;
    const int wm = warp >> 2, wn = warp & 3;
    const int g = lane >> 2, t4 = lane & 3;
    const int m3 = lane >> 3, rr = lane & 7;
    const int aRowOff = ((m3 & 1) << 3) + rr, aColOff = (m3 >> 1) << 3;
    const int bRowOff = ((m3 >> 1) << 3) + rr, bColOff = (m3 & 1) << 3;
    const int bz = blockIdx.z;
    const int q0 = blockIdx.x * 128;

    const bf16* Am[2] = { Phi + ((size_t)bz*NSEQ + q0)*NSEQ,
                          Plo + ((size_t)bz*NSEQ + q0)*NSEQ };
    const bf16* Bm[2] = { Vthi + (size_t)bz*D_*NSEQ,
                          Vtlo + (size_t)bz*D_*NSEQ };

    float acc[2][8][4] = {};

    av_load_chunk(Am, Bm, smb, 0, tid);
    CP_COMMIT();

    for (int ch = 0; ch < AV_NCHUNK; ch++) {
        uint32_t sbase = smb + (uint32_t)(ch & 1) * (AV_STAGE_EL*2u);
        CP_WAIT0();
        __syncthreads();
        if (ch + 1 < AV_NCHUNK) {
            av_load_chunk(Am, Bm, smb + (uint32_t)((ch+1)&1) * (AV_STAGE_EL*2u), (ch+1)*32, tid);
            CP_COMMIT();
        }
        #pragma unroll
        for (int ks = 0; ks < 2; ks++) {
            const int kb0 = ks*16;
            unsigned bF[2][8][2];
            #pragma unroll
            for (int mat = 0; mat < 2; mat++)
                #pragma unroll
                for (int p = 0; p < 4; p++) {
                    int N0 = wn*64 + p*16;
                    uint32_t addr = sbase + (uint32_t)(10240 + mat*10240 + (N0 + bRowOff)*40 + kb0 + bColOff)*2u;
                    unsigned r[4]; ldsm_x4(addr, r);
                    bF[mat][2*p  ][0]=r[0]; bF[mat][2*p  ][1]=r[1];
                    bF[mat][2*p+1][0]=r[2]; bF[mat][2*p+1][1]=r[3];
                }
            #pragma unroll
            for (int mt = 0; mt < 2; mt++) {
                int R = wm*32 + mt*16;
                unsigned a0[4], a1[4];
                uint32_t abase = sbase + (uint32_t)((R + aRowOff)*40 + kb0 + aColOff)*2u;
                ldsm_x4(abase,          a0);   // Phi
                ldsm_x4(abase + 10240u, a1);   // Plo
                #pragma unroll
                for (int nt=0; nt<8; nt++) {
                    mma16816(acc[mt][nt], a0, bF[0][nt]);
                    mma16816(acc[mt][nt], a0, bF[1][nt]);
                    mma16816(acc[mt][nt], a1, bF[0][nt]);
                }
            }
        }
        __syncthreads();
    }

    float* ob = Qh + ((size_t)bz*NSEQ + q0)*D_;
    #pragma unroll
    for (int mt=0; mt<2; mt++)
        #pragma unroll
        for (int nt=0; nt<8; nt++) {
            int r = wm*32 + mt*16 + g;
            int c = wn*64 + nt*8 + 2*t4;
            float2 v0 = { acc[mt][nt][0], acc[mt][nt][1] };
            float2 v1 = { acc[mt][nt][2], acc[mt][nt][3] };
            *(float2*)(ob + (size_t)r*D_ + c)     = v0;
            *(float2*)(ob + (size_t)(r+8)*D_ + c) = v1;
        }
}

// ======================= in-place row softmax (4096) + hi/lo ================
__device__ __forceinline__ float blockMax256(float v) {
    __shared__ float sh[8];
    #pragma unroll
    for (int o=16;o>0;o>>=1) v = fmaxf(v, __shfl_xor_sync(0xffffffffu, v, o));
    if ((threadIdx.x & 31)==0) sh[threadIdx.x>>5] = v;
    __syncthreads();
    float m = sh[0];
    #pragma unroll
    for (int w=1;w<8;w++) m = fmaxf(m, sh[w]);
    __syncthreads();
    return m;
}
__device__ __forceinline__ float blockSum256(float v) {
    __shared__ float sh[8];
    #pragma unroll
    for (int o=16;o>0;o>>=1) v += __shfl_xor_sync(0xffffffffu, v, o);
    if ((threadIdx.x & 31)==0) sh[threadIdx.x>>5] = v;
    __syncthreads();
    float s = sh[0];
    #pragma unroll
    for (int w=1;w<8;w++) s += sh[w];
    __syncthreads();
    return s;
}
__global__ __launch_bounds__(256) void softmax_kernel(
    float* __restrict__ attn, bf16* __restrict__ Phi, bf16* __restrict__ Plo)
{
    size_t rb = (size_t)blockIdx.x * NSEQ;
    float4* p = (float4*)(attn + rb);
    int tid = threadIdx.x;
    float4 v[4];
    #pragma unroll
    for (int t=0;t<4;t++) v[t] = p[tid + 256*t];
    float m = -1e30f;
    #pragma unroll
    for (int t=0;t<4;t++)
        m = fmaxf(m, fmaxf(fmaxf(v[t].x, v[t].y), fmaxf(v[t].z, v[t].w)));
    m = blockMax256(m);
    float s = 0.f;
    #pragma unroll
    for (int t=0;t<4;t++) {
        v[t].x = __expf(v[t].x - m); v[t].y = __expf(v[t].y - m);
        v[t].z = __expf(v[t].z - m); v[t].w = __expf(v[t].w - m);
        s += v[t].x + v[t].y + v[t].z + v[t].w;
    }
    s = blockSum256(s);
    float inv = 1.0f / s;
    #pragma unroll
    for (int t=0;t<4;t++) {
        v[t].x *= inv; v[t].y *= inv; v[t].z *= inv; v[t].w *= inv;
        p[tid + 256*t] = v[t];
        int idx = (tid + 256*t)*4;
        float f[4] = {v[t].x, v[t].y, v[t].z, v[t].w};
        bf16 h[4], l[4];
        #pragma unroll
        for (int u=0;u<4;u++) split_bf16(f[u], h[u], l[u]);
        __nv_bfloat162 h01; h01.x=h[0]; h01.y=h[1];
        __nv_bfloat162 h23; h23.x=h[2]; h23.y=h[3];
        __nv_bfloat162 l01; l01.x=l[0]; l01.y=l[1];
        __nv_bfloat162 l23; l23.x=l[2]; l23.y=l[3];
        __nv_bfloat162* hp = (__nv_bfloat162*)(Phi + rb + idx);
        __nv_bfloat162* lp = (__nv_bfloat162*)(Plo + rb + idx);
        hp[0]=h01; hp[1]=h23; lp[0]=l01; lp[1]=l23;
    }
}

// ===================== fused gate epilogue ==================================
__device__ __forceinline__ void blockSum2_128(float& a, float& b) {
    __shared__ float sh[8];
    #pragma unroll
    for (int o=16;o>0;o>>=1) {
        a += __shfl_xor_sync(0xffffffffu, a, o);
        b += __shfl_xor_sync(0xffffffffu, b, o);
    }
    if ((threadIdx.x & 31)==0) { sh[threadIdx.x>>5]=a; sh[4+(threadIdx.x>>5)]=b; }
    __syncthreads();
    a = sh[0]+sh[1]+sh[2]+sh[3];
    b = sh[4]+sh[5]+sh[6]+sh[7];
    __syncthreads();
}

__global__ __launch_bounds__(128) void epilogue_kernel(
    const float* __restrict__ Qg, const float* __restrict__ Qhg,
    const float* __restrict__ W1, const float* __restrict__ b1,
    const float* __restrict__ W2, const float* __restrict__ b2,
    const float* __restrict__ W3, const float* __restrict__ b3,
    const float* __restrict__ Wc, const float* __restrict__ bc,
    const float* __restrict__ Wf, const float* __restrict__ bf,
    const float* __restrict__ gg, const float* __restrict__ gb,
    const float* __restrict__ eg, const float* __restrict__ eb,
    float* __restrict__ out)
{
    __shared__ float Qs[EROWS][D_];
    __shared__ float Qh[EROWS][D_];
    __shared__ float ges[EROWS][NOUT];
    int j = threadIdx.x;
    size_t row0 = (size_t)blockIdx.x * EROWS;

    {
        const float4* s1 = (const float4*)(Qg  + row0*D_);
        const float4* s2 = (const float4*)(Qhg + row0*D_);
        float4* dQ = (float4*)&Qs[0][0];
        float4* dH = (float4*)&Qh[0][0];
        for (int t=j; t<EROWS*D_/4; t+=128) { dQ[t]=s1[t]; dH[t]=s2[t]; }
    }
    __syncthreads();

    float acc1[EROWS]={}, acc2[EROWS]={}, acc3[EROWS]={}, accF[EROWS]={};
    for (int c=0; c<D_; c+=4) {
        float w1v[4], w2v[4], w3v[4], wfv[4];
        #pragma unroll
        for (int u=0;u<4;u++) {
            w1v[u]=W1[(c+u)*NOUT+j]; w2v[u]=W2[(c+u)*NOUT+j];
            w3v[u]=W3[(c+u)*NOUT+j]; wfv[u]=Wf[(c+u)*NOUT+j];
        }
        #pragma unroll
        for (int r=0;r<EROWS;r++) {
            float4 q = *(const float4*)&Qs[r][c];
            float4 h = *(const float4*)&Qh[r][c];
            acc1[r] += q.x*w1v[0]+q.y*w1v[1]+q.z*w1v[2]+q.w*w1v[3];
            accF[r] += q.x*wfv[0]+q.y*wfv[1]+q.z*wfv[2]+q.w*wfv[3];
            acc2[r] += h.x*w2v[0]+h.y*w2v[1]+h.z*w2v[2]+h.w*w2v[3];
            acc3[r] += h.x*w3v[0]+h.y*w3v[1]+h.z*w3v[2]+h.w*w3v[3];
        }
    }

    float bb1=b1[j], bb2=b2[j], bb3=b3[j], bbf=bf[j], bbc=bc[j];
    float ggj=gg[j], gbj=gb[j], egj=eg[j], ebj=eb[j];

    #pragma unroll 1
    for (int r=0;r<EROWS;r++) {
        float gin = fmaxf(fmaxf(acc1[r]+bb1,0.f) + fmaxf(acc2[r]+bb2,0.f), 0.f);
        float ein = fmaxf(acc3[r]+bb3, 0.f);
        float s1 = gin, s2 = gin*gin;
        blockSum2_128(s1, s2);
        float mu  = s1*(1.0f/NOUT);
        float var = s2*(1.0f/NOUT) - mu*mu;
        float G = (gin-mu)*rsqrtf(var+EPS)*ggj + gbj;
        s1 = ein; s2 = ein*ein;
        blockSum2_128(s1, s2);
        mu  = s1*(1.0f/NOUT);
        var = s2*(1.0f/NOUT) - mu*mu;
        float E = (ein-mu)*rsqrtf(var+EPS)*egj + ebj;
        ges[r][j] = G*E;
        accF[r] = fmaxf(accF[r]+bbf, 0.f);
    }
    __syncthreads();

    float accC[EROWS]={};
    for (int k=0;k<NOUT;k++) {
        float wc = Wc[k*NOUT+j];
        #pragma unroll
        for (int r=0;r<EROWS;r++) accC[r] += ges[r][k]*wc;
    }
    #pragma unroll
    for (int r=0;r<EROWS;r++)
        out[(row0+r)*NOUT + j] = accF[r] + fmaxf(accC[r]+bbc, 0.f);
}

// ============================================================================
extern "C" void kernel_launch(void* const* d_in, const int* in_sizes, int n_in,
                              void* d_out, int out_size)
{
    const float* x1 = (const float*)d_in[0];
    const float* x2 = (const float*)d_in[1];
    const float* W_q=(const float*)d_in[2];  const float* b_q=(const float*)d_in[3];
    const float* W_k=(const float*)d_in[4];  const float* b_k=(const float*)d_in[5];
    const float* W_v=(const float*)d_in[6];  const float* b_v=(const float*)d_in[7];
    const float* W1 =(const float*)d_in[8];  const float* b1 =(const float*)d_in[9];
    const float* W2 =(const float*)d_in[10]; const float* b2 =(const float*)d_in[11];
    const float* W3 =(const float*)d_in[12]; const float* b3 =(const float*)d_in[13];
    const float* gg =(const float*)d_in[14]; const float* gb =(const float*)d_in[15];
    const float* eg =(const float*)d_in[16]; const float* eb =(const float*)d_in[17];
    const float* Wc =(const float*)d_in[18]; const float* bc =(const float*)d_in[19];
    const float* Wf =(const float*)d_in[20]; const float* bf =(const float*)d_in[21];

    float* out     = (float*)d_out;
    float* outMain = out;
    float* attn    = out + (size_t)MTOT*NOUT;

    float *Q,*Qh;
    bf16 *Qhi,*Qlo,*tQhi,*tQlo,*Khi,*Klo,*tKhi,*tKlo,*Vthi,*Vtlo,*Phi,*Plo;
    cudaGetSymbolAddress((void**)&Q,   g_Q);
    cudaGetSymbolAddress((void**)&Qh,  g_Qh);
    cudaGetSymbolAddress((void**)&Qhi, g_Qhi);  cudaGetSymbolAddress((void**)&Qlo, g_Qlo);
    cudaGetSymbolAddress((void**)&tQhi,g_tQhi); cudaGetSymbolAddress((void**)&tQlo,g_tQlo);
    cudaGetSymbolAddress((void**)&Khi, g_Khi);  cudaGetSymbolAddress((void**)&Klo, g_Klo);
    cudaGetSymbolAddress((void**)&tKhi,g_tKhi); cudaGetSymbolAddress((void**)&tKlo,g_tKlo);
    cudaGetSymbolAddress((void**)&Vthi,g_Vthi); cudaGetSymbolAddress((void**)&Vtlo,g_Vtlo);
    cudaGetSymbolAddress((void**)&Phi, g_Phi);  cudaGetSymbolAddress((void**)&Plo, g_Plo);

    cudaFuncSetAttribute(scores_mma_kernel, cudaFuncAttributeMaxDynamicSharedMemorySize, 2*SC_STAGE_EL*2);
    cudaFuncSetAttribute(av_mma_kernel,     cudaFuncAttributeMaxDynamicSharedMemorySize, 2*AV_STAGE_EL*2);

    dim3 pg(D_/64, MTOT/64);
    proj_kernel<0><<<pg, 256>>>(x2, W_q, b_q, Q, Qhi, Qlo, tQhi, tQlo);
    proj_kernel<1><<<pg, 256>>>(x1, W_k, b_k, nullptr, Khi, Klo, tKhi, tKlo);
    proj_kernel<2><<<pg, 256>>>(x1, W_v, b_v, nullptr, Vthi, Vtlo, nullptr, nullptr);

    scores_mma_kernel<<<dim3(NSEQ/128, NSEQ/128, B_), 512, 2*SC_STAGE_EL*2>>>(
        Qhi, Qlo, tQhi, tQlo, Khi, Klo, tKhi, tKlo, attn);

    softmax_kernel<<<MTOT, 256>>>(attn, Phi, Plo);

    av_mma_kernel<<<dim3(NSEQ/128, 1, B_), 512, 2*AV_STAGE_EL*2>>>(Phi, Plo, Vthi, Vtlo, Qh);

    epilogue_kernel<<<MTOT/EROWS, 128>>>(Q, Qh, W1,b1, W2,b2, W3,b3,
                                         Wc,bc, Wf,bf, gg,gb, eg,eb, outMain);
}

// round 11
// speedup vs baseline: 2.8102x; 1.1141x over previous
#include <cuda_runtime.h>
#include <cuda_bf16.h>
#include <cuda_fp16.h>
#include <stdint.h>
#include <math.h>

#define B_    4
#define NSEQ  4096
#define MTOT  (B_*NSEQ)
#define D_    256
#define NOUT  128
#define EPS   1e-5f
#define EROWS 16

typedef __nv_bfloat16 bf16;

// ---- scratch (static device globals; no allocation allowed) ----
__device__ float  g_Q [(size_t)MTOT*D_];
__device__ float  g_Qh[(size_t)MTOT*D_];
__device__ __half g_Qhi16[(size_t)MTOT*D_], g_Qlo16[(size_t)MTOT*D_];
__device__ __half g_K16  [(size_t)MTOT*D_];
__device__ bf16   g_tQhi[(size_t)MTOT*D_], g_tQlo[(size_t)MTOT*D_];
__device__ bf16   g_tKhi[(size_t)MTOT*D_], g_tKlo[(size_t)MTOT*D_];
__device__ bf16   g_Vthi[(size_t)MTOT*D_], g_Vtlo[(size_t)MTOT*D_];   // [B][D][NSEQ]
__device__ bf16   g_Phi [(size_t)B_*NSEQ*NSEQ], g_Plo[(size_t)B_*NSEQ*NSEQ];

__device__ __forceinline__ void split_bf16(float x, bf16& h, bf16& l) {
    h = __float2bfloat16(x);
    l = __float2bfloat16(x - __bfloat162float(h));
}
__device__ __forceinline__ void split_f16(float x, __half& h, __half& l) {
    h = __float2half_rn(x);
    l = __float2half_rn(x - __half2float(h));
}

__device__ __forceinline__ uint32_t smem_u32(const void* p) {
    uint32_t a;
    asm("{ .reg .u64 t; cvta.to.shared.u64 t, %1; cvt.u32.u64 %0, t; }" : "=r"(a) : "l"(p));
    return a;
}

#define CP_ASYNC16(dst, src) \
    asm volatile("cp.async.cg.shared.global [%0], [%1], 16;" :: "r"(dst), "l"(src) : "memory")
#define CP_COMMIT() asm volatile("cp.async.commit_group;" ::: "memory")
#define CP_WAIT1()  asm volatile("cp.async.wait_group 1;" ::: "memory")

// bf16 m16n8k16 mma, fp32 accum
__device__ __forceinline__ void mma16816(float* d, const unsigned* a, const unsigned* b) {
    asm volatile(
        "mma.sync.aligned.m16n8k16.row.col.f32.bf16.bf16.f32 "
        "{%0,%1,%2,%3}, {%4,%5,%6,%7}, {%8,%9}, {%0,%1,%2,%3};\n"
        : "+f"(d[0]), "+f"(d[1]), "+f"(d[2]), "+f"(d[3])
        : "r"(a[0]), "r"(a[1]), "r"(a[2]), "r"(a[3]), "r"(b[0]), "r"(b[1]));
}
// fp16 m16n8k16 mma, fp32 accum
__device__ __forceinline__ void mma16816h(float* d, const unsigned* a, const unsigned* b) {
    asm volatile(
        "mma.sync.aligned.m16n8k16.row.col.f32.f16.f16.f32 "
        "{%0,%1,%2,%3}, {%4,%5,%6,%7}, {%8,%9}, {%0,%1,%2,%3};\n"
        : "+f"(d[0]), "+f"(d[1]), "+f"(d[2]), "+f"(d[3])
        : "r"(a[0]), "r"(a[1]), "r"(a[2]), "r"(a[3]), "r"(b[0]), "r"(b[1]));
}

__device__ __forceinline__ void ldsm_x4(uint32_t addr, unsigned* r) {
    asm volatile("ldmatrix.sync.aligned.m8n8.x4.shared.b16 {%0,%1,%2,%3}, [%4];"
        : "=r"(r[0]), "=r"(r[1]), "=r"(r[2]), "=r"(r[3]) : "r"(addr));
}

// ================= Q projection: Q = x2@Wq + bq ============================
__global__ __launch_bounds__(256) void proj_q_kernel(
    const float* __restrict__ X, const float* __restrict__ W,
    const float* __restrict__ bias, float* __restrict__ Cf,
    __half* __restrict__ H1, __half* __restrict__ L1,
    bf16* __restrict__ H2, bf16* __restrict__ L2)
{
    const int BM=64, BN=64, BK=16;
    __shared__ float Xs[BK][BM];
    __shared__ float Ws[BK][BN];
    int tid = threadIdx.x;
    int tx = tid & 15, ty = tid >> 4;
    int row0 = blockIdx.y * BM;
    int col0 = blockIdx.x * BN;
    int lr = tid >> 2, lc4 = tid & 3;
    int wkr = tid >> 4, wc4 = tid & 15;
    float acc[4][4] = {};

    for (int k0 = 0; k0 < D_; k0 += BK) {
        float4 v = *(const float4*)(X + (size_t)(row0+lr)*D_ + k0 + lc4*4);
        Xs[lc4*4+0][lr]=v.x; Xs[lc4*4+1][lr]=v.y; Xs[lc4*4+2][lr]=v.z; Xs[lc4*4+3][lr]=v.w;
        *(float4*)&Ws[wkr][wc4*4] = *(const float4*)(W + (size_t)(k0+wkr)*D_ + col0 + wc4*4);
        __syncthreads();
        #pragma unroll
        for (int kk=0; kk<BK; kk++) {
            float4 a4 = *(const float4*)&Xs[kk][ty*4];
            float4 w4 = *(const float4*)&Ws[kk][tx*4];
            float av[4]={a4.x,a4.y,a4.z,a4.w}, wv[4]={w4.x,w4.y,w4.z,w4.w};
            #pragma unroll
            for (int i=0;i<4;i++)
                #pragma unroll
                for (int j=0;j<4;j++) acc[i][j] += av[i]*wv[j];
        }
        __syncthreads();
    }
    #pragma unroll
    for (int i=0;i<4;i++) {
        size_t r = row0 + ty*4 + i;
        #pragma unroll
        for (int j=0;j<4;j++) {
            int cix = col0 + tx*4 + j;
            float val = acc[i][j] + bias[cix];
            Cf[r*D_ + cix] = val;
            __half hh,hl; split_f16(val, hh, hl);
            H1[r*D_+cix]=hh; L1[r*D_+cix]=hl;
            float t = tanhf(val);
            bf16 h,l; split_bf16(t, h, l);
            H2[r*D_+cix]=h; L2[r*D_+cix]=l;
        }
    }
}

// ============== merged K+V projection from x1 ==============================
__global__ __launch_bounds__(256) void proj_kv_kernel(
    const float* __restrict__ X,
    const float* __restrict__ Wk, const float* __restrict__ bk,
    const float* __restrict__ Wv, const float* __restrict__ bv,
    __half* __restrict__ K16,
    bf16* __restrict__ tKh, bf16* __restrict__ tKl,
    bf16* __restrict__ Vth, bf16* __restrict__ Vtl)
{
    const int BM=64, BN=64, BK=16;
    __shared__ float Xs [BK][BM];
    __shared__ float WsK[BK][BN];
    __shared__ float WsV[BK][BN];
    int tid = threadIdx.x;
    int tx = tid & 15, ty = tid >> 4;
    int row0 = blockIdx.y * BM;
    int col0 = blockIdx.x * BN;
    int lr = tid >> 2, lc4 = tid & 3;
    int wkr = tid >> 4, wc4 = tid & 15;
    float accK[4][4] = {}, accV[4][4] = {};

    for (int k0 = 0; k0 < D_; k0 += BK) {
        float4 v = *(const float4*)(X + (size_t)(row0+lr)*D_ + k0 + lc4*4);
        Xs[lc4*4+0][lr]=v.x; Xs[lc4*4+1][lr]=v.y; Xs[lc4*4+2][lr]=v.z; Xs[lc4*4+3][lr]=v.w;
        *(float4*)&WsK[wkr][wc4*4] = *(const float4*)(Wk + (size_t)(k0+wkr)*D_ + col0 + wc4*4);
        *(float4*)&WsV[wkr][wc4*4] = *(const float4*)(Wv + (size_t)(k0+wkr)*D_ + col0 + wc4*4);
        __syncthreads();
        #pragma unroll
        for (int kk=0; kk<BK; kk++) {
            float4 a4 = *(const float4*)&Xs[kk][ty*4];
            float4 k4 = *(const float4*)&WsK[kk][tx*4];
            float4 v4 = *(const float4*)&WsV[kk][tx*4];
            float av[4]={a4.x,a4.y,a4.z,a4.w};
            float kv[4]={k4.x,k4.y,k4.z,k4.w}, vv[4]={v4.x,v4.y,v4.z,v4.w};
            #pragma unroll
            for (int i=0;i<4;i++)
                #pragma unroll
                for (int j=0;j<4;j++) {
                    accK[i][j] += av[i]*kv[j];
                    accV[i][j] += av[i]*vv[j];
                }
        }
        __syncthreads();
    }
    #pragma unroll
    for (int i=0;i<4;i++) {
        size_t r = row0 + ty*4 + i;
        int b = (int)(r >> 12), s = (int)(r & 4095);
        #pragma unroll
        for (int j=0;j<4;j++) {
            int cix = col0 + tx*4 + j;
            float valK = accK[i][j] + bk[cix];
            K16[r*D_+cix] = __float2half_rn(valK);
            float t = tanhf(valK);
            bf16 h,l; split_bf16(t, h, l);
            tKh[r*D_+cix]=h; tKl[r*D_+cix]=l;
            float valV = accV[i][j] + bv[cix];
            size_t ti = ((size_t)b*D_ + cix)*NSEQ + s;
            split_bf16(valV, h, l);
            Vth[ti]=h; Vtl[ti]=l;
        }
    }
}

// ====== dual-GEMM scores: 7 mats, fp16-asym QK + bf16 3-term tanh ==========
// stage: mats 0..6 = Qhi16,Qlo16,tQhi,tQlo,K16,tKhi,tKlo; mat m at m*5120 el,
// rows padded to 40 el. stage = 7*5120 el = 71680 B. 3 stages.
#define SC_STAGE_EL 35840
#define SC_STAGE_B  71680

__device__ __forceinline__ void sc_load_chunk(
    const bf16* const* P, uint32_t stage_b, int kc, int tid)
{
    #pragma unroll
    for (int t=0;t<7;t++) {
        int i = tid + t*512;                    // 0..3583
        int m = i >> 9, rem = i & 511, row = rem >> 2, c8 = rem & 3;
        const bf16* src = P[m] + (size_t)row*D_ + kc + c8*8;
        uint32_t dst = stage_b + (uint32_t)(m*5120 + row*40 + c8*8)*2u;
        CP_ASYNC16(dst, src);
    }
}

__global__ __launch_bounds__(512,1) void scores_mma_kernel(
    const __half* __restrict__ Qhi16, const __half* __restrict__ Qlo16,
    const bf16* __restrict__ tQhi, const bf16* __restrict__ tQlo,
    const __half* __restrict__ K16,
    const bf16* __restrict__ tKhi, const bf16* __restrict__ tKlo,
    float* __restrict__ attn)
{
    extern __shared__ __align__(16) bf16 sm[];
    const uint32_t smb = smem_u32(sm);
    const int tid = threadIdx.x;
    const int warp = tid >> 5, lane = tid & 31;
    const int wm = warp >> 2, wn = warp & 3;
    const int g = lane >> 2, t4 = lane & 3;
    const int m3 = lane >> 3, rr = lane & 7;
    const int aRowOff = ((m3 & 1) << 3) + rr, aColOff = (m3 >> 1) << 3;
    const int bRowOff = ((m3 >> 1) << 3) + rr, bColOff = (m3 & 1) << 3;
    const int bz = blockIdx.z;
    const int q0 = blockIdx.y * 128, c0 = blockIdx.x * 128;

    const bf16* P[7] = {
        (const bf16*)(Qhi16 + ((size_t)bz*NSEQ + q0)*D_),
        (const bf16*)(Qlo16 + ((size_t)bz*NSEQ + q0)*D_),
        tQhi + ((size_t)bz*NSEQ + q0)*D_,
        tQlo + ((size_t)bz*NSEQ + q0)*D_,
        (const bf16*)(K16 + ((size_t)bz*NSEQ + c0)*D_),
        tKhi + ((size_t)bz*NSEQ + c0)*D_,
        tKlo + ((size_t)bz*NSEQ + c0)*D_ };

    float accQ[2][4][4] = {};
    float accT[2][4][4] = {};

    sc_load_chunk(P, smb, 0, tid);  CP_COMMIT();
    sc_load_chunk(P, smb + SC_STAGE_B, 32, tid);  CP_COMMIT();

    for (int ch = 0; ch < 8; ch++) {
        uint32_t sbase = smb + (uint32_t)(ch % 3) * SC_STAGE_B;
        CP_WAIT1();
        __syncthreads();
        if (ch + 2 < 8)
            sc_load_chunk(P, smb + (uint32_t)((ch+2) % 3) * SC_STAGE_B, (ch+2)*32, tid);
        CP_COMMIT();
        #pragma unroll
        for (int ks = 0; ks < 2; ks++) {
            const int kb0 = ks*16;
            // B fragments: mats 4(K16), 5(tKhi), 6(tKlo)
            unsigned bF[3][4][2];
            #pragma unroll
            for (int mb = 0; mb < 3; mb++)
                #pragma unroll
                for (int p = 0; p < 2; p++) {
                    int N0 = wn*32 + p*16;
                    uint32_t addr = sbase + (uint32_t)((4+mb)*5120 + (N0 + bRowOff)*40 + kb0 + bColOff)*2u;
                    unsigned r[4]; ldsm_x4(addr, r);
                    bF[mb][2*p  ][0]=r[0]; bF[mb][2*p  ][1]=r[1];
                    bF[mb][2*p+1][0]=r[2]; bF[mb][2*p+1][1]=r[3];
                }
            #pragma unroll
            for (int mt = 0; mt < 2; mt++) {
                int R = wm*32 + mt*16;
                unsigned a0[4], a1[4], a2[4], a3[4];
                uint32_t abase = sbase + (uint32_t)((R + aRowOff)*40 + kb0 + aColOff)*2u;
                ldsm_x4(abase,            a0);   // Qhi16
                ldsm_x4(abase + 10240u,   a1);   // Qlo16
                ldsm_x4(abase + 20480u,   a2);   // tQhi
                ldsm_x4(abase + 30720u,   a3);   // tQlo
                #pragma unroll
                for (int nt=0; nt<4; nt++) {
                    mma16816h(accQ[mt][nt], a0, bF[0][nt]);
                    mma16816h(accQ[mt][nt], a1, bF[0][nt]);
                    mma16816 (accT[mt][nt], a2, bF[1][nt]);
                    mma16816 (accT[mt][nt], a2, bF[2][nt]);
                    mma16816 (accT[mt][nt], a3, bF[1][nt]);
                }
            }
        }
        // no bottom barrier: next iteration's __syncthreads orders reuse
    }

    float* ob = attn + (size_t)bz*NSEQ*NSEQ;
    #pragma unroll
    for (int mt=0; mt<2; mt++)
        #pragma unroll
        for (int nt=0; nt<4; nt++) {
            int r = q0 + wm*32 + mt*16 + g;
            int c = c0 + wn*32 + nt*8 + 2*t4;
            const float* aq = accQ[mt][nt];
            const float* at = accT[mt][nt];
            float2 v0 = { aq[0]*(at[0]+1.0f)*0.03125f, aq[1]*(at[1]+1.0f)*0.03125f };
            float2 v1 = { aq[2]*(at[2]+1.0f)*0.03125f, aq[3]*(at[3]+1.0f)*0.03125f };
            *(float2*)(ob + (size_t)r*NSEQ + c)     = v0;
            *(float2*)(ob + (size_t)(r+8)*NSEQ + c) = v1;
        }
}

// ========================= Qhat = attn @ V (3-stage) ========================
#define AV_STAGE_EL 30720
#define AV_STAGE_B  61440
#define AV_NCHUNK  (NSEQ/32)

__device__ __forceinline__ void av_load_chunk(
    const bf16* const* Am, const bf16* const* Bm, uint32_t stage_b, int kc, int tid)
{
    #pragma unroll
    for (int t=0;t<6;t++) {
        int i = tid + t*512;
        const bf16* src; uint32_t dst;
        if (i < 1024) {
            int m = i >> 9, rem = i & 511, row = rem >> 2, c8 = rem & 3;
            src = Am[m] + (size_t)row*NSEQ + kc + c8*8;
            dst = stage_b + (uint32_t)(m*5120 + row*40 + c8*8)*2u;
        } else {
            int j = i - 1024;
            int m = j >> 10, rem = j & 1023, row = rem >> 2, c8 = rem & 3;
            src = Bm[m] + (size_t)row*NSEQ + kc + c8*8;
            dst = stage_b + (uint32_t)(10240 + m*10240 + row*40 + c8*8)*2u;
        }
        CP_ASYNC16(dst, src);
    }
}

__global__ __launch_bounds__(512,1) void av_mma_kernel(
    const bf16* __restrict__ Phi, const bf16* __restrict__ Plo,
    const bf16* __restrict__ Vthi, const bf16* __restrict__ Vtlo,
    float* __restrict__ Qh)
{
    extern __shared__ __align__(16) bf16 sm[];
    const uint32_t smb = smem_u32(sm);
    const int tid = threadIdx.x;
    const int warp = tid >> 5, lane = tid & 31;
    const int wm = warp >> 2, wn = warp & 3;
    const int g = lane >> 2, t4 = lane & 3;
    const int m3 = lane >> 3, rr = lane & 7;
    const int aRowOff = ((m3 & 1) << 3) + rr, aColOff = (m3 >> 1) << 3;
    const int bRowOff = ((m3 >> 1) << 3) + rr, bColOff = (m3 & 1) << 3;
    const int bz = blockIdx.z;
    const int q0 = blockIdx.x * 128;

    const bf16* Am[2] = { Phi + ((size_t)bz*NSEQ + q0)*NSEQ,
                          Plo + ((size_t)bz*NSEQ + q0)*NSEQ };
    const bf16* Bm[2] = { Vthi + (size_t)bz*D_*NSEQ,
                          Vtlo + (size_t)bz*D_*NSEQ };

    float acc[2][8][4] = {};

    av_load_chunk(Am, Bm, smb, 0, tid);  CP_COMMIT();
    av_load_chunk(Am, Bm, smb + AV_STAGE_B, 32, tid);  CP_COMMIT();

    for (int ch = 0; ch < AV_NCHUNK; ch++) {
        uint32_t sbase = smb + (uint32_t)(ch % 3) * AV_STAGE_B;
        CP_WAIT1();
        __syncthreads();
        if (ch + 2 < AV_NCHUNK)
            av_load_chunk(Am, Bm, smb + (uint32_t)((ch+2) % 3) * AV_STAGE_B, (ch+2)*32, tid);
        CP_COMMIT();
        #pragma unroll
        for (int ks = 0; ks < 2; ks++) {
            const int kb0 = ks*16;
            unsigned bF[2][8][2];
            #pragma unroll
            for (int mat = 0; mat < 2; mat++)
                #pragma unroll
                for (int p = 0; p < 4; p++) {
                    int N0 = wn*64 + p*16;
                    uint32_t addr = sbase + (uint32_t)(10240 + mat*10240 + (N0 + bRowOff)*40 + kb0 + bColOff)*2u;
                    unsigned r[4]; ldsm_x4(addr, r);
                    bF[mat][2*p  ][0]=r[0]; bF[mat][2*p  ][1]=r[1];
                    bF[mat][2*p+1][0]=r[2]; bF[mat][2*p+1][1]=r[3];
                }
            #pragma unroll
            for (int mt = 0; mt < 2; mt++) {
                int R = wm*32 + mt*16;
                unsigned a0[4], a1[4];
                uint32_t abase = sbase + (uint32_t)((R + aRowOff)*40 + kb0 + aColOff)*2u;
                ldsm_x4(abase,          a0);   // Phi
                ldsm_x4(abase + 10240u, a1);   // Plo
                #pragma unroll
                for (int nt=0; nt<8; nt++) {
                    mma16816(acc[mt][nt], a0, bF[0][nt]);
                    mma16816(acc[mt][nt], a0, bF[1][nt]);
                    mma16816(acc[mt][nt], a1, bF[0][nt]);
                }
            }
        }
        // no bottom barrier
    }

    float* ob = Qh + ((size_t)bz*NSEQ + q0)*D_;
    #pragma unroll
    for (int mt=0; mt<2; mt++)
        #pragma unroll
        for (int nt=0; nt<8; nt++) {
            int r = wm*32 + mt*16 + g;
            int c = wn*64 + nt*8 + 2*t4;
            float2 v0 = { acc[mt][nt][0], acc[mt][nt][1] };
            float2 v1 = { acc[mt][nt][2], acc[mt][nt][3] };
            *(float2*)(ob + (size_t)r*D_ + c)     = v0;
            *(float2*)(ob + (size_t)(r+8)*D_ + c) = v1;
        }
}

// ======================= in-place row softmax (4096) + hi/lo ================
__device__ __forceinline__ float blockMax256(float v) {
    __shared__ float sh[8];
    #pragma unroll
    for (int o=16;o>0;o>>=1) v = fmaxf(v, __shfl_xor_sync(0xffffffffu, v, o));
    if ((threadIdx.x & 31)==0) sh[threadIdx.x>>5] = v;
    __syncthreads();
    float m = sh[0];
    #pragma unroll
    for (int w=1;w<8;w++) m = fmaxf(m, sh[w]);
    __syncthreads();
    return m;
}
__device__ __forceinline__ float blockSum256(float v) {
    __shared__ float sh[8];
    #pragma unroll
    for (int o=16;o>0;o>>=1) v += __shfl_xor_sync(0xffffffffu, v, o);
    if ((threadIdx.x & 31)==0) sh[threadIdx.x>>5] = v;
    __syncthreads();
    float s = sh[0];
    #pragma unroll
    for (int w=1;w<8;w++) s += sh[w];
    __syncthreads();
    return s;
}
__global__ __launch_bounds__(256) void softmax_kernel(
    float* __restrict__ attn, bf16* __restrict__ Phi, bf16* __restrict__ Plo)
{
    size_t rb = (size_t)blockIdx.x * NSEQ;
    float4* p = (float4*)(attn + rb);
    int tid = threadIdx.x;
    float4 v[4];
    #pragma unroll
    for (int t=0;t<4;t++) v[t] = p[tid + 256*t];
    float m = -1e30f;
    #pragma unroll
    for (int t=0;t<4;t++)
        m = fmaxf(m, fmaxf(fmaxf(v[t].x, v[t].y), fmaxf(v[t].z, v[t].w)));
    m = blockMax256(m);
    float s = 0.f;
    #pragma unroll
    for (int t=0;t<4;t++) {
        v[t].x = __expf(v[t].x - m); v[t].y = __expf(v[t].y - m);
        v[t].z = __expf(v[t].z - m); v[t].w = __expf(v[t].w - m);
        s += v[t].x + v[t].y + v[t].z + v[t].w;
    }
    s = blockSum256(s);
    float inv = 1.0f / s;
    #pragma unroll
    for (int t=0;t<4;t++) {
        v[t].x *= inv; v[t].y *= inv; v[t].z *= inv; v[t].w *= inv;
        p[tid + 256*t] = v[t];
        int idx = (tid + 256*t)*4;
        float f[4] = {v[t].x, v[t].y, v[t].z, v[t].w};
        bf16 h[4], l[4];
        #pragma unroll
        for (int u=0;u<4;u++) split_bf16(f[u], h[u], l[u]);
        __nv_bfloat162 h01; h01.x=h[0]; h01.y=h[1];
        __nv_bfloat162 h23; h23.x=h[2]; h23.y=h[3];
        __nv_bfloat162 l01; l01.x=l[0]; l01.y=l[1];
        __nv_bfloat162 l23; l23.x=l[2]; l23.y=l[3];
        __nv_bfloat162* hp = (__nv_bfloat162*)(Phi + rb + idx);
        __nv_bfloat162* lp = (__nv_bfloat162*)(Plo + rb + idx);
        hp[0]=h01; hp[1]=h23; lp[0]=l01; lp[1]=l23;
    }
}

// ===================== fused gate epilogue ==================================
__device__ __forceinline__ void blockSum2_128(float& a, float& b) {
    __shared__ float sh[8];
    #pragma unroll
    for (int o=16;o>0;o>>=1) {
        a += __shfl_xor_sync(0xffffffffu, a, o);
        b += __shfl_xor_sync(0xffffffffu, b, o);
    }
    if ((threadIdx.x & 31)==0) { sh[threadIdx.x>>5]=a; sh[4+(threadIdx.x>>5)]=b; }
    __syncthreads();
    a = sh[0]+sh[1]+sh[2]+sh[3];
    b = sh[4]+sh[5]+sh[6]+sh[7];
    __syncthreads();
}

__global__ __launch_bounds__(128) void epilogue_kernel(
    const float* __restrict__ Qg, const float* __restrict__ Qhg,
    const float* __restrict__ W1, const float* __restrict__ b1,
    const float* __restrict__ W2, const float* __restrict__ b2,
    const float* __restrict__ W3, const float* __restrict__ b3,
    const float* __restrict__ Wc, const float* __restrict__ bc,
    const float* __restrict__ Wf, const float* __restrict__ bf,
    const float* __restrict__ gg, const float* __restrict__ gb,
    const float* __restrict__ eg, const float* __restrict__ eb,
    float* __restrict__ out)
{
    __shared__ float Qs[EROWS][D_];
    __shared__ float Qh[EROWS][D_];
    __shared__ float ges[EROWS][NOUT];
    int j = threadIdx.x;
    size_t row0 = (size_t)blockIdx.x * EROWS;

    {
        const float4* s1 = (const float4*)(Qg  + row0*D_);
        const float4* s2 = (const float4*)(Qhg + row0*D_);
        float4* dQ = (float4*)&Qs[0][0];
        float4* dH = (float4*)&Qh[0][0];
        for (int t=j; t<EROWS*D_/4; t+=128) { dQ[t]=s1[t]; dH[t]=s2[t]; }
    }
    __syncthreads();

    float acc1[EROWS]={}, acc2[EROWS]={}, acc3[EROWS]={}, accF[EROWS]={};
    for (int c=0; c<D_; c+=4) {
        float w1v[4], w2v[4], w3v[4], wfv[4];
        #pragma unroll
        for (int u=0;u<4;u++) {
            w1v[u]=W1[(c+u)*NOUT+j]; w2v[u]=W2[(c+u)*NOUT+j];
            w3v[u]=W3[(c+u)*NOUT+j]; wfv[u]=Wf[(c+u)*NOUT+j];
        }
        #pragma unroll
        for (int r=0;r<EROWS;r++) {
            float4 q = *(const float4*)&Qs[r][c];
            float4 h = *(const float4*)&Qh[r][c];
            acc1[r] += q.x*w1v[0]+q.y*w1v[1]+q.z*w1v[2]+q.w*w1v[3];
            accF[r] += q.x*wfv[0]+q.y*wfv[1]+q.z*wfv[2]+q.w*wfv[3];
            acc2[r] += h.x*w2v[0]+h.y*w2v[1]+h.z*w2v[2]+h.w*w2v[3];
            acc3[r] += h.x*w3v[0]+h.y*w3v[1]+h.z*w3v[2]+h.w*w3v[3];
        }
    }

    float bb1=b1[j], bb2=b2[j], bb3=b3[j], bbf=bf[j], bbc=bc[j];
    float ggj=gg[j], gbj=gb[j], egj=eg[j], ebj=eb[j];

    #pragma unroll 1
    for (int r=0;r<EROWS;r++) {
        float gin = fmaxf(fmaxf(acc1[r]+bb1,0.f) + fmaxf(acc2[r]+bb2,0.f), 0.f);
        float ein = fmaxf(acc3[r]+bb3, 0.f);
        float s1 = gin, s2 = gin*gin;
        blockSum2_128(s1, s2);
        float mu  = s1*(1.0f/NOUT);
        float var = s2*(1.0f/NOUT) - mu*mu;
        float G = (gin-mu)*rsqrtf(var+EPS)*ggj + gbj;
        s1 = ein; s2 = ein*ein;
        blockSum2_128(s1, s2);
        mu  = s1*(1.0f/NOUT);
        var = s2*(1.0f/NOUT) - mu*mu;
        float E = (ein-mu)*rsqrtf(var+EPS)*egj + ebj;
        ges[r][j] = G*E;
        accF[r] = fmaxf(accF[r]+bbf, 0.f);
    }
    __syncthreads();

    float accC[EROWS]={};
    for (int k=0;k<NOUT;k++) {
        float wc = Wc[k*NOUT+j];
        #pragma unroll
        for (int r=0;r<EROWS;r++) accC[r] += ges[r][k]*wc;
    }
    #pragma unroll
    for (int r=0;r<EROWS;r++)
        out[(row0+r)*NOUT + j] = accF[r] + fmaxf(accC[r]+bbc, 0.f);
}

// ============================================================================
extern "C" void kernel_launch(void* const* d_in, const int* in_sizes, int n_in,
                              void* d_out, int out_size)
{
    const float* x1 = (const float*)d_in[0];
    const float* x2 = (const float*)d_in[1];
    const float* W_q=(const float*)d_in[2];  const float* b_q=(const float*)d_in[3];
    const float* W_k=(const float*)d_in[4];  const float* b_k=(const float*)d_in[5];
    const float* W_v=(const float*)d_in[6];  const float* b_v=(const float*)d_in[7];
    const float* W1 =(const float*)d_in[8];  const float* b1 =(const float*)d_in[9];
    const float* W2 =(const float*)d_in[10]; const float* b2 =(const float*)d_in[11];
    const float* W3 =(const float*)d_in[12]; const float* b3 =(const float*)d_in[13];
    const float* gg =(const float*)d_in[14]; const float* gb =(const float*)d_in[15];
    const float* eg =(const float*)d_in[16]; const float* eb =(const float*)d_in[17];
    const float* Wc =(const float*)d_in[18]; const float* bc =(const float*)d_in[19];
    const float* Wf =(const float*)d_in[20]; const float* bf =(const float*)d_in[21];

    float* out     = (float*)d_out;
    float* outMain = out;
    float* attn    = out + (size_t)MTOT*NOUT;

    float *Q,*Qh;
    __half *Qhi16,*Qlo16,*K16;
    bf16 *tQhi,*tQlo,*tKhi,*tKlo,*Vthi,*Vtlo,*Phi,*Plo;
    cudaGetSymbolAddress((void**)&Q,     g_Q);
    cudaGetSymbolAddress((void**)&Qh,    g_Qh);
    cudaGetSymbolAddress((void**)&Qhi16, g_Qhi16); cudaGetSymbolAddress((void**)&Qlo16, g_Qlo16);
    cudaGetSymbolAddress((void**)&K16,   g_K16);
    cudaGetSymbolAddress((void**)&tQhi,  g_tQhi);  cudaGetSymbolAddress((void**)&tQlo, g_tQlo);
    cudaGetSymbolAddress((void**)&tKhi,  g_tKhi);  cudaGetSymbolAddress((void**)&tKlo, g_tKlo);
    cudaGetSymbolAddress((void**)&Vthi,  g_Vthi);  cudaGetSymbolAddress((void**)&Vtlo, g_Vtlo);
    cudaGetSymbolAddress((void**)&Phi,   g_Phi);   cudaGetSymbolAddress((void**)&Plo,  g_Plo);

    cudaFuncSetAttribute(scores_mma_kernel, cudaFuncAttributeMaxDynamicSharedMemorySize, 3*SC_STAGE_B);
    cudaFuncSetAttribute(av_mma_kernel,     cudaFuncAttributeMaxDynamicSharedMemorySize, 3*AV_STAGE_B);

    dim3 pg(D_/64, MTOT/64);
    proj_q_kernel <<<pg, 256>>>(x2, W_q, b_q, Q, Qhi16, Qlo16, tQhi, tQlo);
    proj_kv_kernel<<<pg, 256>>>(x1, W_k, b_k, W_v, b_v, K16, tKhi, tKlo, Vthi, Vtlo);

    scores_mma_kernel<<<dim3(NSEQ/128, NSEQ/128, B_), 512, 3*SC_STAGE_B>>>(
        Qhi16, Qlo16, tQhi, tQlo, K16, tKhi, tKlo, attn);

    softmax_kernel<<<MTOT, 256>>>(attn, Phi, Plo);

    av_mma_kernel<<<dim3(NSEQ/128, 1, B_), 512, 3*AV_STAGE_B>>>(Phi, Plo, Vthi, Vtlo, Qh);

    epilogue_kernel<<<MTOT/EROWS, 128>>>(Q, Qh, W1,b1, W2,b2, W3,b3,
                                         Wc,bc, Wf,bf, gg,gb, eg,eb, outMain);
}

// round 12
// speedup vs baseline: 3.0477x; 1.0845x over previous
#include <cuda_runtime.h>
#include <cuda_bf16.h>
#include <cuda_fp16.h>
#include <stdint.h>
#include <math.h>

#define B_    4
#define NSEQ  4096
#define MTOT  (B_*NSEQ)
#define D_    256
#define NOUT  128
#define EPS   1e-5f
#define EROWS 16

typedef __nv_bfloat16 bf16;

// ---- scratch (static device globals; no allocation allowed) ----
__device__ float  g_Q [(size_t)MTOT*D_];
__device__ float  g_Qh[(size_t)MTOT*D_];
__device__ __half g_Qhi16[(size_t)MTOT*D_], g_Qlo16[(size_t)MTOT*D_];
__device__ __half g_K16  [(size_t)MTOT*D_];
__device__ bf16   g_tQhi[(size_t)MTOT*D_], g_tQlo[(size_t)MTOT*D_];
__device__ bf16   g_tKhi[(size_t)MTOT*D_], g_tKlo[(size_t)MTOT*D_];
__device__ __half g_Vt16[(size_t)MTOT*D_];                           // [B][D][NSEQ]
__device__ __half g_Phi16[(size_t)B_*NSEQ*NSEQ], g_Plo16[(size_t)B_*NSEQ*NSEQ];

__device__ __forceinline__ void split_bf16(float x, bf16& h, bf16& l) {
    h = __float2bfloat16(x);
    l = __float2bfloat16(x - __bfloat162float(h));
}
__device__ __forceinline__ void split_f16(float x, __half& h, __half& l) {
    h = __float2half_rn(x);
    l = __float2half_rn(x - __half2float(h));
}

__device__ __forceinline__ uint32_t smem_u32(const void* p) {
    uint32_t a;
    asm("{ .reg .u64 t; cvta.to.shared.u64 t, %1; cvt.u32.u64 %0, t; }" : "=r"(a) : "l"(p));
    return a;
}

#define CP_ASYNC16(dst, src) \
    asm volatile("cp.async.cg.shared.global [%0], [%1], 16;" :: "r"(dst), "l"(src) : "memory")
#define CP_COMMIT() asm volatile("cp.async.commit_group;" ::: "memory")
#define CP_WAIT1()  asm volatile("cp.async.wait_group 1;" ::: "memory")

// bf16 m16n8k16 mma, fp32 accum
__device__ __forceinline__ void mma16816(float* d, const unsigned* a, const unsigned* b) {
    asm volatile(
        "mma.sync.aligned.m16n8k16.row.col.f32.bf16.bf16.f32 "
        "{%0,%1,%2,%3}, {%4,%5,%6,%7}, {%8,%9}, {%0,%1,%2,%3};\n"
        : "+f"(d[0]), "+f"(d[1]), "+f"(d[2]), "+f"(d[3])
        : "r"(a[0]), "r"(a[1]), "r"(a[2]), "r"(a[3]), "r"(b[0]), "r"(b[1]));
}
// fp16 m16n8k16 mma, fp32 accum
__device__ __forceinline__ void mma16816h(float* d, const unsigned* a, const unsigned* b) {
    asm volatile(
        "mma.sync.aligned.m16n8k16.row.col.f32.f16.f16.f32 "
        "{%0,%1,%2,%3}, {%4,%5,%6,%7}, {%8,%9}, {%0,%1,%2,%3};\n"
        : "+f"(d[0]), "+f"(d[1]), "+f"(d[2]), "+f"(d[3])
        : "r"(a[0]), "r"(a[1]), "r"(a[2]), "r"(a[3]), "r"(b[0]), "r"(b[1]));
}

__device__ __forceinline__ void ldsm_x4(uint32_t addr, unsigned* r) {
    asm volatile("ldmatrix.sync.aligned.m8n8.x4.shared.b16 {%0,%1,%2,%3}, [%4];"
        : "=r"(r[0]), "=r"(r[1]), "=r"(r[2]), "=r"(r[3]) : "r"(addr));
}

// ================= Q projection: Q = x2@Wq + bq ============================
__global__ __launch_bounds__(256) void proj_q_kernel(
    const float* __restrict__ X, const float* __restrict__ W,
    const float* __restrict__ bias, float* __restrict__ Cf,
    __half* __restrict__ H1, __half* __restrict__ L1,
    bf16* __restrict__ H2, bf16* __restrict__ L2)
{
    const int BM=64, BN=64, BK=16;
    __shared__ float Xs[BK][BM];
    __shared__ float Ws[BK][BN];
    int tid = threadIdx.x;
    int tx = tid & 15, ty = tid >> 4;
    int row0 = blockIdx.y * BM;
    int col0 = blockIdx.x * BN;
    int lr = tid >> 2, lc4 = tid & 3;
    int wkr = tid >> 4, wc4 = tid & 15;
    float acc[4][4] = {};

    for (int k0 = 0; k0 < D_; k0 += BK) {
        float4 v = *(const float4*)(X + (size_t)(row0+lr)*D_ + k0 + lc4*4);
        Xs[lc4*4+0][lr]=v.x; Xs[lc4*4+1][lr]=v.y; Xs[lc4*4+2][lr]=v.z; Xs[lc4*4+3][lr]=v.w;
        *(float4*)&Ws[wkr][wc4*4] = *(const float4*)(W + (size_t)(k0+wkr)*D_ + col0 + wc4*4);
        __syncthreads();
        #pragma unroll
        for (int kk=0; kk<BK; kk++) {
            float4 a4 = *(const float4*)&Xs[kk][ty*4];
            float4 w4 = *(const float4*)&Ws[kk][tx*4];
            float av[4]={a4.x,a4.y,a4.z,a4.w}, wv[4]={w4.x,w4.y,w4.z,w4.w};
            #pragma unroll
            for (int i=0;i<4;i++)
                #pragma unroll
                for (int j=0;j<4;j++) acc[i][j] += av[i]*wv[j];
        }
        __syncthreads();
    }
    #pragma unroll
    for (int i=0;i<4;i++) {
        size_t r = row0 + ty*4 + i;
        #pragma unroll
        for (int j=0;j<4;j++) {
            int cix = col0 + tx*4 + j;
            float val = acc[i][j] + bias[cix];
            Cf[r*D_ + cix] = val;
            __half hh,hl; split_f16(val, hh, hl);
            H1[r*D_+cix]=hh; L1[r*D_+cix]=hl;
            float t = tanhf(val);
            bf16 h,l; split_bf16(t, h, l);
            H2[r*D_+cix]=h; L2[r*D_+cix]=l;
        }
    }
}

// ============== merged K+V projection from x1 ==============================
__global__ __launch_bounds__(256) void proj_kv_kernel(
    const float* __restrict__ X,
    const float* __restrict__ Wk, const float* __restrict__ bk,
    const float* __restrict__ Wv, const float* __restrict__ bv,
    __half* __restrict__ K16,
    bf16* __restrict__ tKh, bf16* __restrict__ tKl,
    __half* __restrict__ Vt16)
{
    const int BM=64, BN=64, BK=16;
    __shared__ float Xs [BK][BM];
    __shared__ float WsK[BK][BN];
    __shared__ float WsV[BK][BN];
    int tid = threadIdx.x;
    int tx = tid & 15, ty = tid >> 4;
    int row0 = blockIdx.y * BM;
    int col0 = blockIdx.x * BN;
    int lr = tid >> 2, lc4 = tid & 3;
    int wkr = tid >> 4, wc4 = tid & 15;
    float accK[4][4] = {}, accV[4][4] = {};

    for (int k0 = 0; k0 < D_; k0 += BK) {
        float4 v = *(const float4*)(X + (size_t)(row0+lr)*D_ + k0 + lc4*4);
        Xs[lc4*4+0][lr]=v.x; Xs[lc4*4+1][lr]=v.y; Xs[lc4*4+2][lr]=v.z; Xs[lc4*4+3][lr]=v.w;
        *(float4*)&WsK[wkr][wc4*4] = *(const float4*)(Wk + (size_t)(k0+wkr)*D_ + col0 + wc4*4);
        *(float4*)&WsV[wkr][wc4*4] = *(const float4*)(Wv + (size_t)(k0+wkr)*D_ + col0 + wc4*4);
        __syncthreads();
        #pragma unroll
        for (int kk=0; kk<BK; kk++) {
            float4 a4 = *(const float4*)&Xs[kk][ty*4];
            float4 k4 = *(const float4*)&WsK[kk][tx*4];
            float4 v4 = *(const float4*)&WsV[kk][tx*4];
            float av[4]={a4.x,a4.y,a4.z,a4.w};
            float kv[4]={k4.x,k4.y,k4.z,k4.w}, vv[4]={v4.x,v4.y,v4.z,v4.w};
            #pragma unroll
            for (int i=0;i<4;i++)
                #pragma unroll
                for (int j=0;j<4;j++) {
                    accK[i][j] += av[i]*kv[j];
                    accV[i][j] += av[i]*vv[j];
                }
        }
        __syncthreads();
    }
    #pragma unroll
    for (int i=0;i<4;i++) {
        size_t r = row0 + ty*4 + i;
        int b = (int)(r >> 12), s = (int)(r & 4095);
        #pragma unroll
        for (int j=0;j<4;j++) {
            int cix = col0 + tx*4 + j;
            float valK = accK[i][j] + bk[cix];
            K16[r*D_+cix] = __float2half_rn(valK);
            float t = tanhf(valK);
            bf16 h,l; split_bf16(t, h, l);
            tKh[r*D_+cix]=h; tKl[r*D_+cix]=l;
            float valV = accV[i][j] + bv[cix];
            size_t ti = ((size_t)b*D_ + cix)*NSEQ + s;
            Vt16[ti] = __float2half_rn(valV);
        }
    }
}

// ====== dual-GEMM scores: 7 mats, fp16-asym QK + bf16 3-term tanh ==========
#define SC_STAGE_EL 35840
#define SC_STAGE_B  71680

__device__ __forceinline__ void sc_load_chunk(
    const bf16* const* P, uint32_t stage_b, int kc, int tid)
{
    #pragma unroll
    for (int t=0;t<7;t++) {
        int i = tid + t*512;                    // 0..3583
        int m = i >> 9, rem = i & 511, row = rem >> 2, c8 = rem & 3;
        const bf16* src = P[m] + (size_t)row*D_ + kc + c8*8;
        uint32_t dst = stage_b + (uint32_t)(m*5120 + row*40 + c8*8)*2u;
        CP_ASYNC16(dst, src);
    }
}

__global__ __launch_bounds__(512,1) void scores_mma_kernel(
    const __half* __restrict__ Qhi16, const __half* __restrict__ Qlo16,
    const bf16* __restrict__ tQhi, const bf16* __restrict__ tQlo,
    const __half* __restrict__ K16,
    const bf16* __restrict__ tKhi, const bf16* __restrict__ tKlo,
    float* __restrict__ attn)
{
    extern __shared__ __align__(16) bf16 sm[];
    const uint32_t smb = smem_u32(sm);
    const int tid = threadIdx.x;
    const int warp = tid >> 5, lane = tid & 31;
    const int wm = warp >> 2, wn = warp & 3;
    const int g = lane >> 2, t4 = lane & 3;
    const int m3 = lane >> 3, rr = lane & 7;
    const int aRowOff = ((m3 & 1) << 3) + rr, aColOff = (m3 >> 1) << 3;
    const int bRowOff = ((m3 >> 1) << 3) + rr, bColOff = (m3 & 1) << 3;
    const int bz = blockIdx.z;
    const int q0 = blockIdx.y * 128, c0 = blockIdx.x * 128;

    const bf16* P[7] = {
        (const bf16*)(Qhi16 + ((size_t)bz*NSEQ + q0)*D_),
        (const bf16*)(Qlo16 + ((size_t)bz*NSEQ + q0)*D_),
        tQhi + ((size_t)bz*NSEQ + q0)*D_,
        tQlo + ((size_t)bz*NSEQ + q0)*D_,
        (const bf16*)(K16 + ((size_t)bz*NSEQ + c0)*D_),
        tKhi + ((size_t)bz*NSEQ + c0)*D_,
        tKlo + ((size_t)bz*NSEQ + c0)*D_ };

    float accQ[2][4][4] = {};
    float accT[2][4][4] = {};

    sc_load_chunk(P, smb, 0, tid);  CP_COMMIT();
    sc_load_chunk(P, smb + SC_STAGE_B, 32, tid);  CP_COMMIT();

    for (int ch = 0; ch < 8; ch++) {
        uint32_t sbase = smb + (uint32_t)(ch % 3) * SC_STAGE_B;
        CP_WAIT1();
        __syncthreads();
        if (ch + 2 < 8)
            sc_load_chunk(P, smb + (uint32_t)((ch+2) % 3) * SC_STAGE_B, (ch+2)*32, tid);
        CP_COMMIT();
        #pragma unroll
        for (int ks = 0; ks < 2; ks++) {
            const int kb0 = ks*16;
            unsigned bF[3][4][2];
            #pragma unroll
            for (int mb = 0; mb < 3; mb++)
                #pragma unroll
                for (int p = 0; p < 2; p++) {
                    int N0 = wn*32 + p*16;
                    uint32_t addr = sbase + (uint32_t)((4+mb)*5120 + (N0 + bRowOff)*40 + kb0 + bColOff)*2u;
                    unsigned r[4]; ldsm_x4(addr, r);
                    bF[mb][2*p  ][0]=r[0]; bF[mb][2*p  ][1]=r[1];
                    bF[mb][2*p+1][0]=r[2]; bF[mb][2*p+1][1]=r[3];
                }
            #pragma unroll
            for (int mt = 0; mt < 2; mt++) {
                int R = wm*32 + mt*16;
                unsigned a0[4], a1[4], a2[4], a3[4];
                uint32_t abase = sbase + (uint32_t)((R + aRowOff)*40 + kb0 + aColOff)*2u;
                ldsm_x4(abase,            a0);   // Qhi16
                ldsm_x4(abase + 10240u,   a1);   // Qlo16
                ldsm_x4(abase + 20480u,   a2);   // tQhi
                ldsm_x4(abase + 30720u,   a3);   // tQlo
                #pragma unroll
                for (int nt=0; nt<4; nt++) {
                    mma16816h(accQ[mt][nt], a0, bF[0][nt]);
                    mma16816h(accQ[mt][nt], a1, bF[0][nt]);
                    mma16816 (accT[mt][nt], a2, bF[1][nt]);
                    mma16816 (accT[mt][nt], a2, bF[2][nt]);
                    mma16816 (accT[mt][nt], a3, bF[1][nt]);
                }
            }
        }
    }

    float* ob = attn + (size_t)bz*NSEQ*NSEQ;
    #pragma unroll
    for (int mt=0; mt<2; mt++)
        #pragma unroll
        for (int nt=0; nt<4; nt++) {
            int r = q0 + wm*32 + mt*16 + g;
            int c = c0 + wn*32 + nt*8 + 2*t4;
            const float* aq = accQ[mt][nt];
            const float* at = accT[mt][nt];
            float2 v0 = { aq[0]*(at[0]+1.0f)*0.03125f, aq[1]*(at[1]+1.0f)*0.03125f };
            float2 v1 = { aq[2]*(at[2]+1.0f)*0.03125f, aq[3]*(at[3]+1.0f)*0.03125f };
            *(float2*)(ob + (size_t)r*NSEQ + c)     = v0;
            *(float2*)(ob + (size_t)(r+8)*NSEQ + c) = v1;
        }
}

// ========= Qhat = attn @ V — fp16 asym: P hi/lo fp16 × V fp16 ===============
// stage: A mats Phi16,Plo16 at 0,5120 el; B mat Vt16 at 10240 el (256 rows).
// stage = 20480 el = 40960 B. 3 stages.
#define AV_STAGE_EL 20480
#define AV_STAGE_B  40960
#define AV_NCHUNK  (NSEQ/32)

__device__ __forceinline__ void av_load_chunk(
    const __half* const* Am, const __half* Bm, uint32_t stage_b, int kc, int tid)
{
    #pragma unroll
    for (int t=0;t<4;t++) {
        int i = tid + t*512;                   // 0..2047
        const __half* src; uint32_t dst;
        if (i < 1024) {
            int m = i >> 9, rem = i & 511, row = rem >> 2, c8 = rem & 3;
            src = Am[m] + (size_t)row*NSEQ + kc + c8*8;
            dst = stage_b + (uint32_t)(m*5120 + row*40 + c8*8)*2u;
        } else {
            int j = i - 1024;                  // 0..1023
            int row = j >> 2, c8 = j & 3;      // 256 rows
            src = Bm + (size_t)row*NSEQ + kc + c8*8;
            dst = stage_b + (uint32_t)(10240 + row*40 + c8*8)*2u;
        }
        CP_ASYNC16(dst, src);
    }
}

__global__ __launch_bounds__(512,1) void av_mma_kernel(
    const __half* __restrict__ Phi16, const __half* __restrict__ Plo16,
    const __half* __restrict__ Vt16,
    float* __restrict__ Qh)
{
    extern __shared__ __align__(16) bf16 sm[];
    const uint32_t smb = smem_u32(sm);
    const int tid = threadIdx.x;
    const int warp = tid >> 5, lane = tid & 31;
    const int wm = warp >> 2, wn = warp & 3;
    const int g = lane >> 2, t4 = lane & 3;
    const int m3 = lane >> 3, rr = lane & 7;
    const int aRowOff = ((m3 & 1) << 3) + rr, aColOff = (m3 >> 1) << 3;
    const int bRowOff = ((m3 >> 1) << 3) + rr, bColOff = (m3 & 1) << 3;
    const int bz = blockIdx.z;
    const int q0 = blockIdx.x * 128;

    const __half* Am[2] = { Phi16 + ((size_t)bz*NSEQ + q0)*NSEQ,
                            Plo16 + ((size_t)bz*NSEQ + q0)*NSEQ };
    const __half* Bm = Vt16 + (size_t)bz*D_*NSEQ;

    float acc[2][8][4] = {};

    av_load_chunk(Am, Bm, smb, 0, tid);  CP_COMMIT();
    av_load_chunk(Am, Bm, smb + AV_STAGE_B, 32, tid);  CP_COMMIT();

    for (int ch = 0; ch < AV_NCHUNK; ch++) {
        uint32_t sbase = smb + (uint32_t)(ch % 3) * AV_STAGE_B;
        CP_WAIT1();
        __syncthreads();
        if (ch + 2 < AV_NCHUNK)
            av_load_chunk(Am, Bm, smb + (uint32_t)((ch+2) % 3) * AV_STAGE_B, (ch+2)*32, tid);
        CP_COMMIT();
        #pragma unroll
        for (int ks = 0; ks < 2; ks++) {
            const int kb0 = ks*16;
            unsigned bF[8][2];
            #pragma unroll
            for (int p = 0; p < 4; p++) {
                int N0 = wn*64 + p*16;
                uint32_t addr = sbase + (uint32_t)(10240 + (N0 + bRowOff)*40 + kb0 + bColOff)*2u;
                unsigned r[4]; ldsm_x4(addr, r);
                bF[2*p  ][0]=r[0]; bF[2*p  ][1]=r[1];
                bF[2*p+1][0]=r[2]; bF[2*p+1][1]=r[3];
            }
            #pragma unroll
            for (int mt = 0; mt < 2; mt++) {
                int R = wm*32 + mt*16;
                unsigned a0[4], a1[4];
                uint32_t abase = sbase + (uint32_t)((R + aRowOff)*40 + kb0 + aColOff)*2u;
                ldsm_x4(abase,          a0);   // Phi16
                ldsm_x4(abase + 10240u, a1);   // Plo16
                #pragma unroll
                for (int nt=0; nt<8; nt++) {
                    mma16816h(acc[mt][nt], a0, bF[nt]);
                    mma16816h(acc[mt][nt], a1, bF[nt]);
                }
            }
        }
    }

    float* ob = Qh + ((size_t)bz*NSEQ + q0)*D_;
    #pragma unroll
    for (int mt=0; mt<2; mt++)
        #pragma unroll
        for (int nt=0; nt<8; nt++) {
            int r = wm*32 + mt*16 + g;
            int c = wn*64 + nt*8 + 2*t4;
            float2 v0 = { acc[mt][nt][0], acc[mt][nt][1] };
            float2 v1 = { acc[mt][nt][2], acc[mt][nt][3] };
            *(float2*)(ob + (size_t)r*D_ + c)     = v0;
            *(float2*)(ob + (size_t)(r+8)*D_ + c) = v1;
        }
}

// ======================= in-place row softmax (4096) + fp16 hi/lo ===========
__device__ __forceinline__ float blockMax256(float v) {
    __shared__ float sh[8];
    #pragma unroll
    for (int o=16;o>0;o>>=1) v = fmaxf(v, __shfl_xor_sync(0xffffffffu, v, o));
    if ((threadIdx.x & 31)==0) sh[threadIdx.x>>5] = v;
    __syncthreads();
    float m = sh[0];
    #pragma unroll
    for (int w=1;w<8;w++) m = fmaxf(m, sh[w]);
    __syncthreads();
    return m;
}
__device__ __forceinline__ float blockSum256(float v) {
    __shared__ float sh[8];
    #pragma unroll
    for (int o=16;o>0;o>>=1) v += __shfl_xor_sync(0xffffffffu, v, o);
    if ((threadIdx.x & 31)==0) sh[threadIdx.x>>5] = v;
    __syncthreads();
    float s = sh[0];
    #pragma unroll
    for (int w=1;w<8;w++) s += sh[w];
    __syncthreads();
    return s;
}
__global__ __launch_bounds__(256) void softmax_kernel(
    float* __restrict__ attn, __half* __restrict__ Phi, __half* __restrict__ Plo)
{
    size_t rb = (size_t)blockIdx.x * NSEQ;
    float4* p = (float4*)(attn + rb);
    int tid = threadIdx.x;
    float4 v[4];
    #pragma unroll
    for (int t=0;t<4;t++) v[t] = p[tid + 256*t];
    float m = -1e30f;
    #pragma unroll
    for (int t=0;t<4;t++)
        m = fmaxf(m, fmaxf(fmaxf(v[t].x, v[t].y), fmaxf(v[t].z, v[t].w)));
    m = blockMax256(m);
    float s = 0.f;
    #pragma unroll
    for (int t=0;t<4;t++) {
        v[t].x = __expf(v[t].x - m); v[t].y = __expf(v[t].y - m);
        v[t].z = __expf(v[t].z - m); v[t].w = __expf(v[t].w - m);
        s += v[t].x + v[t].y + v[t].z + v[t].w;
    }
    s = blockSum256(s);
    float inv = 1.0f / s;
    #pragma unroll
    for (int t=0;t<4;t++) {
        v[t].x *= inv; v[t].y *= inv; v[t].z *= inv; v[t].w *= inv;
        p[tid + 256*t] = v[t];
        int idx = (tid + 256*t)*4;
        float f[4] = {v[t].x, v[t].y, v[t].z, v[t].w};
        __half h[4], l[4];
        #pragma unroll
        for (int u=0;u<4;u++) split_f16(f[u], h[u], l[u]);
        __half2 h01; h01.x=h[0]; h01.y=h[1];
        __half2 h23; h23.x=h[2]; h23.y=h[3];
        __half2 l01; l01.x=l[0]; l01.y=l[1];
        __half2 l23; l23.x=l[2]; l23.y=l[3];
        __half2* hp = (__half2*)(Phi + rb + idx);
        __half2* lp = (__half2*)(Plo + rb + idx);
        hp[0]=h01; hp[1]=h23; lp[0]=l01; lp[1]=l23;
    }
}

// ===================== fused gate epilogue ==================================
__device__ __forceinline__ void blockSum2_128(float& a, float& b) {
    __shared__ float sh[8];
    #pragma unroll
    for (int o=16;o>0;o>>=1) {
        a += __shfl_xor_sync(0xffffffffu, a, o);
        b += __shfl_xor_sync(0xffffffffu, b, o);
    }
    if ((threadIdx.x & 31)==0) { sh[threadIdx.x>>5]=a; sh[4+(threadIdx.x>>5)]=b; }
    __syncthreads();
    a = sh[0]+sh[1]+sh[2]+sh[3];
    b = sh[4]+sh[5]+sh[6]+sh[7];
    __syncthreads();
}

__global__ __launch_bounds__(128) void epilogue_kernel(
    const float* __restrict__ Qg, const float* __restrict__ Qhg,
    const float* __restrict__ W1, const float* __restrict__ b1,
    const float* __restrict__ W2, const float* __restrict__ b2,
    const float* __restrict__ W3, const float* __restrict__ b3,
    const float* __restrict__ Wc, const float* __restrict__ bc,
    const float* __restrict__ Wf, const float* __restrict__ bf,
    const float* __restrict__ gg, const float* __restrict__ gb,
    const float* __restrict__ eg, const float* __restrict__ eb,
    float* __restrict__ out)
{
    __shared__ float Qs[EROWS][D_];
    __shared__ float Qh[EROWS][D_];
    __shared__ float ges[EROWS][NOUT];
    int j = threadIdx.x;
    size_t row0 = (size_t)blockIdx.x * EROWS;

    {
        const float4* s1 = (const float4*)(Qg  + row0*D_);
        const float4* s2 = (const float4*)(Qhg + row0*D_);
        float4* dQ = (float4*)&Qs[0][0];
        float4* dH = (float4*)&Qh[0][0];
        for (int t=j; t<EROWS*D_/4; t+=128) { dQ[t]=s1[t]; dH[t]=s2[t]; }
    }
    __syncthreads();

    float acc1[EROWS]={}, acc2[EROWS]={}, acc3[EROWS]={}, accF[EROWS]={};
    for (int c=0; c<D_; c+=4) {
        float w1v[4], w2v[4], w3v[4], wfv[4];
        #pragma unroll
        for (int u=0;u<4;u++) {
            w1v[u]=W1[(c+u)*NOUT+j]; w2v[u]=W2[(c+u)*NOUT+j];
            w3v[u]=W3[(c+u)*NOUT+j]; wfv[u]=Wf[(c+u)*NOUT+j];
        }
        #pragma unroll
        for (int r=0;r<EROWS;r++) {
            float4 q = *(const float4*)&Qs[r][c];
            float4 h = *(const float4*)&Qh[r][c];
            acc1[r] += q.x*w1v[0]+q.y*w1v[1]+q.z*w1v[2]+q.w*w1v[3];
            accF[r] += q.x*wfv[0]+q.y*wfv[1]+q.z*wfv[2]+q.w*wfv[3];
            acc2[r] += h.x*w2v[0]+h.y*w2v[1]+h.z*w2v[2]+h.w*w2v[3];
            acc3[r] += h.x*w3v[0]+h.y*w3v[1]+h.z*w3v[2]+h.w*w3v[3];
        }
    }

    float bb1=b1[j], bb2=b2[j], bb3=b3[j], bbf=bf[j], bbc=bc[j];
    float ggj=gg[j], gbj=gb[j], egj=eg[j], ebj=eb[j];

    #pragma unroll 1
    for (int r=0;r<EROWS;r++) {
        float gin = fmaxf(fmaxf(acc1[r]+bb1,0.f) + fmaxf(acc2[r]+bb2,0.f), 0.f);
        float ein = fmaxf(acc3[r]+bb3, 0.f);
        float s1 = gin, s2 = gin*gin;
        blockSum2_128(s1, s2);
        float mu  = s1*(1.0f/NOUT);
        float var = s2*(1.0f/NOUT) - mu*mu;
        float G = (gin-mu)*rsqrtf(var+EPS)*ggj + gbj;
        s1 = ein; s2 = ein*ein;
        blockSum2_128(s1, s2);
        mu  = s1*(1.0f/NOUT);
        var = s2*(1.0f/NOUT) - mu*mu;
        float E = (ein-mu)*rsqrtf(var+EPS)*egj + ebj;
        ges[r][j] = G*E;
        accF[r] = fmaxf(accF[r]+bbf, 0.f);
    }
    __syncthreads();

    float accC[EROWS]={};
    for (int k=0;k<NOUT;k++) {
        float wc = Wc[k*NOUT+j];
        #pragma unroll
        for (int r=0;r<EROWS;r++) accC[r] += ges[r][k]*wc;
    }
    #pragma unroll
    for (int r=0;r<EROWS;r++)
        out[(row0+r)*NOUT + j] = accF[r] + fmaxf(accC[r]+bbc, 0.f);
}

// ============================================================================
extern "C" void kernel_launch(void* const* d_in, const int* in_sizes, int n_in,
                              void* d_out, int out_size)
{
    const float* x1 = (const float*)d_in[0];
    const float* x2 = (const float*)d_in[1];
    const float* W_q=(const float*)d_in[2];  const float* b_q=(const float*)d_in[3];
    const float* W_k=(const float*)d_in[4];  const float* b_k=(const float*)d_in[5];
    const float* W_v=(const float*)d_in[6];  const float* b_v=(const float*)d_in[7];
    const float* W1 =(const float*)d_in[8];  const float* b1 =(const float*)d_in[9];
    const float* W2 =(const float*)d_in[10]; const float* b2 =(const float*)d_in[11];
    const float* W3 =(const float*)d_in[12]; const float* b3 =(const float*)d_in[13];
    const float* gg =(const float*)d_in[14]; const float* gb =(const float*)d_in[15];
    const float* eg =(const float*)d_in[16]; const float* eb =(const float*)d_in[17];
    const float* Wc =(const float*)d_in[18]; const float* bc =(const float*)d_in[19];
    const float* Wf =(const float*)d_in[20]; const float* bf =(const float*)d_in[21];

    float* out     = (float*)d_out;
    float* outMain = out;
    float* attn    = out + (size_t)MTOT*NOUT;

    float *Q,*Qh;
    __half *Qhi16,*Qlo16,*K16,*Vt16,*Phi16,*Plo16;
    bf16 *tQhi,*tQlo,*tKhi,*tKlo;
    cudaGetSymbolAddress((void**)&Q,     g_Q);
    cudaGetSymbolAddress((void**)&Qh,    g_Qh);
    cudaGetSymbolAddress((void**)&Qhi16, g_Qhi16); cudaGetSymbolAddress((void**)&Qlo16, g_Qlo16);
    cudaGetSymbolAddress((void**)&K16,   g_K16);
    cudaGetSymbolAddress((void**)&tQhi,  g_tQhi);  cudaGetSymbolAddress((void**)&tQlo, g_tQlo);
    cudaGetSymbolAddress((void**)&tKhi,  g_tKhi);  cudaGetSymbolAddress((void**)&tKlo, g_tKlo);
    cudaGetSymbolAddress((void**)&Vt16,  g_Vt16);
    cudaGetSymbolAddress((void**)&Phi16, g_Phi16); cudaGetSymbolAddress((void**)&Plo16, g_Plo16);

    cudaFuncSetAttribute(scores_mma_kernel, cudaFuncAttributeMaxDynamicSharedMemorySize, 3*SC_STAGE_B);
    cudaFuncSetAttribute(av_mma_kernel,     cudaFuncAttributeMaxDynamicSharedMemorySize, 3*AV_STAGE_B);

    dim3 pg(D_/64, MTOT/64);
    proj_q_kernel <<<pg, 256>>>(x2, W_q, b_q, Q, Qhi16, Qlo16, tQhi, tQlo);
    proj_kv_kernel<<<pg, 256>>>(x1, W_k, b_k, W_v, b_v, K16, tKhi, tKlo, Vt16);

    scores_mma_kernel<<<dim3(NSEQ/128, NSEQ/128, B_), 512, 3*SC_STAGE_B>>>(
        Qhi16, Qlo16, tQhi, tQlo, K16, tKhi, tKlo, attn);

    softmax_kernel<<<MTOT, 256>>>(attn, Phi16, Plo16);

    av_mma_kernel<<<dim3(NSEQ/128, 1, B_), 512, 3*AV_STAGE_B>>>(Phi16, Plo16, Vt16, Qh);

    epilogue_kernel<<<MTOT/EROWS, 128>>>(Q, Qh, W1,b1, W2,b2, W3,b3,
                                         Wc,bc, Wf,bf, gg,gb, eg,eb, outMain);
}